// round 12
// baseline (speedup 1.0000x reference)
#include <cuda_runtime.h>
#include <cuda_bf16.h>
#include <cstdint>
#include <math.h>

#define NB 4
#define NW 2048
#define DM 1024
#define NH 16
#define DK 64
#define MT (NB*NW)
#define MWPR (NW/32)

// ---------------- device scratch ----------------
__device__ unsigned g_mb[NB*NW*MWPR];
__device__ __nv_bfloat16 g_xh[(size_t)MT*DM];   // attn out (hi), written by flash
__device__ __nv_bfloat16 g_xl[(size_t)MT*DM];   // attn out (lo)
__device__ __nv_bfloat16 g_wh[(size_t)DM*DM];   // Wo hi
__device__ __nv_bfloat16 g_wl[(size_t)DM*DM];   // Wo lo
// int8 two-digit quantized inputs/weights for projections
__device__ int8_t g_x8h[(size_t)3*MT*DM];
__device__ int8_t g_x8l[(size_t)3*MT*DM];
__device__ int8_t g_w8h[(size_t)3*DM*DM];
__device__ int8_t g_w8l[(size_t)3*DM*DM];
__device__ float  g_sqx[3*MT];
__device__ float  g_sqw[3*DM];
// projected q/k/v, split bf16, head-major [b][h][t][d]
__device__ __nv_bfloat16 g_qh[NB*NH*NW*DK];
__device__ __nv_bfloat16 g_ql[NB*NH*NW*DK];
__device__ __nv_bfloat16 g_kh[NB*NH*NW*DK];
__device__ __nv_bfloat16 g_kl[NB*NH*NW*DK];
__device__ __nv_bfloat16 g_vh[NB*NH*NW*DK];
__device__ __nv_bfloat16 g_vl[NB*NH*NW*DK];

// ---------------- PTX helpers ----------------
__device__ __forceinline__ uint32_t smem_u32(const void* p) {
    uint32_t a;
    asm("{ .reg .u64 t; cvta.to.shared.u64 t, %1; cvt.u32.u64 %0, t; }" : "=r"(a) : "l"(p));
    return a;
}
#define CP_ASYNC16(sa, g) \
    asm volatile("cp.async.cg.shared.global [%0], [%1], 16;" :: "r"(sa), "l"(g))
#define CP_COMMIT() asm volatile("cp.async.commit_group;" ::: "memory")
#define CP_WAIT1()  asm volatile("cp.async.wait_group 1;" ::: "memory")
#define CP_WAIT0()  asm volatile("cp.async.wait_group 0;" ::: "memory")

#define LDSM4(r, addr) \
    asm volatile("ldmatrix.sync.aligned.m8n8.x4.shared.b16 {%0,%1,%2,%3}, [%4];" \
        : "=r"((r)[0]), "=r"((r)[1]), "=r"((r)[2]), "=r"((r)[3]) : "r"(addr))
#define LDSM4T(r, addr) \
    asm volatile("ldmatrix.sync.aligned.m8n8.x4.trans.shared.b16 {%0,%1,%2,%3}, [%4];" \
        : "=r"((r)[0]), "=r"((r)[1]), "=r"((r)[2]), "=r"((r)[3]) : "r"(addr))

#define MMA16816(d, a, b0, b1) \
    asm volatile("mma.sync.aligned.m16n8k16.row.col.f32.bf16.bf16.f32 " \
        "{%0,%1,%2,%3}, {%4,%5,%6,%7}, {%8,%9}, {%0,%1,%2,%3};" \
        : "+f"((d)[0]), "+f"((d)[1]), "+f"((d)[2]), "+f"((d)[3]) \
        : "r"((a)[0]), "r"((a)[1]), "r"((a)[2]), "r"((a)[3]), "r"(b0), "r"(b1))

#define IMMA16832(d, a, b0, b1) \
    asm volatile("mma.sync.aligned.m16n8k32.row.col.s32.s8.s8.s32 " \
        "{%0,%1,%2,%3}, {%4,%5,%6,%7}, {%8,%9}, {%0,%1,%2,%3};" \
        : "+r"((d)[0]), "+r"((d)[1]), "+r"((d)[2]), "+r"((d)[3]) \
        : "r"((a)[0]), "r"((a)[1]), "r"((a)[2]), "r"((a)[3]), "r"(b0), "r"(b1))

#define PACK_BF16X2(r, lo, hi) \
    asm("cvt.rn.bf16x2.f32 %0, %1, %2;" : "=r"(r) : "f"(hi), "f"(lo))

// ---- bf16 GEMM smem geometry (out_mma only; R8 proven) ----
#define BKC    32
#define RS     40
#define XH_OFF 0
#define XL_OFF 5120
#define WH_OFF 10240
#define WL_OFF 15360
#define STAGE_EL 20480
#define SMEM_MMA (2*STAGE_EL*2)         // 81920 B

// ---- int8 GEMM smem geometry: 4 tiles of 128 rows x 32B, stride 48 ----
#define RSB     48
#define TILE8_B (128*RSB)                // 6144
#define I_XH    0
#define I_XL    TILE8_B
#define I_WH    (2*TILE8_B)
#define I_WL    (3*TILE8_B)
#define STAGE8_B (4*TILE8_B)             // 24576
#define SMEM_I8  (2*STAGE8_B)            // 49152 B

// ---- flash smem geometry ----
#define FRS    72
#define FTS    (64*FRS)
#define FSTAGE (4*FTS)
#define SMEM_FLASH (2*FSTAGE*2)          // 73728 B

#define NWT_ELEMS ((size_t)DM*DM)
#define PACK_BLKS  ((NB*NW*NW)/256)      // 65536
#define XQ_BLKS    (3*MT/8)              // 3072 (8 rows per block)
#define WQ_BLKS    (3*DM/8)              // 384
#define WOC_BLKS   ((int)(NWT_ELEMS/1024))  // 1024
#define PREP_BLKS  (PACK_BLKS + XQ_BLKS + WQ_BLKS + WOC_BLKS)

// ============================================================
// prep helpers
// ============================================================
__device__ __forceinline__ void conv4_store(const float* __restrict__ src, size_t off,
                                            __nv_bfloat16* __restrict__ hi,
                                            __nv_bfloat16* __restrict__ lo, size_t i) {
    float4 v = *(const float4*)(src + off);
    __nv_bfloat16 h0 = __float2bfloat16(v.x), h1 = __float2bfloat16(v.y);
    __nv_bfloat16 h2 = __float2bfloat16(v.z), h3 = __float2bfloat16(v.w);
    __nv_bfloat16 l0 = __float2bfloat16(v.x - __bfloat162float(h0));
    __nv_bfloat16 l1 = __float2bfloat16(v.y - __bfloat162float(h1));
    __nv_bfloat16 l2 = __float2bfloat16(v.z - __bfloat162float(h2));
    __nv_bfloat16 l3 = __float2bfloat16(v.w - __bfloat162float(h3));
    ((__nv_bfloat162*)(hi + i))[0] = __nv_bfloat162(h0, h1);
    ((__nv_bfloat162*)(hi + i))[1] = __nv_bfloat162(h2, h3);
    ((__nv_bfloat162*)(lo + i))[0] = __nv_bfloat162(l0, l1);
    ((__nv_bfloat162*)(lo + i))[1] = __nv_bfloat162(l2, l3);
}

// one warp quantizes one row of 1024 floats -> two int8 digits + scale
__device__ __forceinline__ void quant_row(const float* __restrict__ src,
                                          int8_t* __restrict__ dh, int8_t* __restrict__ dl,
                                          float* __restrict__ sc, int lane) {
    const float4* p = (const float4*)src;
    float4 v[8];
    float mx = 0.f;
    #pragma unroll
    for (int i = 0; i < 8; i++) {
        v[i] = p[lane + 32 * i];
        mx = fmaxf(mx, fmaxf(fmaxf(fabsf(v[i].x), fabsf(v[i].y)),
                             fmaxf(fabsf(v[i].z), fabsf(v[i].w))));
    }
    #pragma unroll
    for (int o = 16; o; o >>= 1) mx = fmaxf(mx, __shfl_xor_sync(0xffffffffu, mx, o));
    if (mx == 0.f) mx = 1.f;
    float inv = 16256.f / mx;
    if (lane == 0) *sc = mx * (1.f / 16256.f);
    uint32_t* dhw = (uint32_t*)dh;
    uint32_t* dlw = (uint32_t*)dl;
    #pragma unroll
    for (int i = 0; i < 8; i++) {
        float q0 = v[i].x * inv, q1 = v[i].y * inv, q2 = v[i].z * inv, q3 = v[i].w * inv;
        float h0 = rintf(q0 * 0.0078125f), h1 = rintf(q1 * 0.0078125f);
        float h2 = rintf(q2 * 0.0078125f), h3 = rintf(q3 * 0.0078125f);
        int l0 = __float2int_rn(q0 - 128.f * h0), l1 = __float2int_rn(q1 - 128.f * h1);
        int l2 = __float2int_rn(q2 - 128.f * h2), l3 = __float2int_rn(q3 - 128.f * h3);
        int i0 = (int)h0, i1 = (int)h1, i2 = (int)h2, i3 = (int)h3;
        dhw[lane + 32 * i] = (i0 & 0xff) | ((i1 & 0xff) << 8) | ((i2 & 0xff) << 16) | ((i3 & 0xff) << 24);
        dlw[lane + 32 * i] = (l0 & 0xff) | ((l1 & 0xff) << 8) | ((l2 & 0xff) << 16) | ((l3 & 0xff) << 24);
    }
}

__global__ void __launch_bounds__(256) prep_kernel(
    const int* __restrict__ mask,
    const float* __restrict__ Q, const float* __restrict__ K, const float* __restrict__ V,
    const float* __restrict__ Wq, const float* __restrict__ Wk,
    const float* __restrict__ Wv, const float* __restrict__ Wo)
{
    int bid = blockIdx.x, tid = threadIdx.x;
    if (bid < PACK_BLKS) {
        int gt = bid * 256 + tid;
        int word = gt >> 5, lane = gt & 31;
        int v = mask[word * 32 + lane];
        unsigned b = __ballot_sync(0xffffffffu, v != 0);
        if (lane == 0) g_mb[word] = b;
        return;
    }
    bid -= PACK_BLKS;
    if (bid < XQ_BLKS) {
        int r = bid * 8 + (tid >> 5);      // 0..24575
        int lane = tid & 31;
        int z = r >> 13, row = r & 8191;
        const float* src = (z == 0) ? Q : (z == 1) ? K : V;
        quant_row(src + (size_t)row * DM, g_x8h + (size_t)r * DM, g_x8l + (size_t)r * DM,
                  g_sqx + r, lane);
        return;
    }
    bid -= XQ_BLKS;
    if (bid < WQ_BLKS) {
        int r = bid * 8 + (tid >> 5);      // 0..3071
        int lane = tid & 31;
        int z = r >> 10, row = r & 1023;
        const float* src = (z == 0) ? Wq : (z == 1) ? Wk : Wv;
        quant_row(src + (size_t)row * DM, g_w8h + (size_t)r * DM, g_w8l + (size_t)r * DM,
                  g_sqw + r, lane);
        return;
    }
    bid -= WQ_BLKS;
    {
        size_t i = ((size_t)bid * 256 + tid) * 4;
        conv4_store(Wo, i, g_wh, g_wl, i);
    }
}

// ============================================================
// int8 projection GEMM: C[128x128] = X * W^T, 2-digit int8, 3 IMMA terms
// 256 threads, 8 warps (4x2), warp 32x64, 2 stages
// ============================================================
__device__ __forceinline__ void issue_stage8(
    const int8_t* __restrict__ xh, const int8_t* __restrict__ xl,
    const int8_t* __restrict__ wh, const int8_t* __restrict__ wl,
    int m0, int n0, int kt, uint32_t stage_sb, int tid)
{
    int row = tid >> 1, half = tid & 1;
    uint32_t so = (uint32_t)(row * RSB + half * 16);
    size_t gx = (size_t)(m0 + row) * DM + kt * 32 + half * 16;
    size_t gw = (size_t)(n0 + row) * DM + kt * 32 + half * 16;
    CP_ASYNC16(stage_sb + I_XH + so, xh + gx);
    CP_ASYNC16(stage_sb + I_XL + so, xl + gx);
    CP_ASYNC16(stage_sb + I_WH + so, wh + gw);
    CP_ASYNC16(stage_sb + I_WL + so, wl + gw);
}

__global__ void __launch_bounds__(256) proj_imma_kernel() {
    extern __shared__ char s8buf[];
    int z = blockIdx.z;
    int m0 = blockIdx.y * 128, n0 = blockIdx.x * 128;
    const int8_t* xh = g_x8h + (size_t)z * MT * DM;
    const int8_t* xl = g_x8l + (size_t)z * MT * DM;
    const int8_t* wh = g_w8h + (size_t)z * DM * DM;
    const int8_t* wl = g_w8l + (size_t)z * DM * DM;
    __nv_bfloat16* dh = (z == 0) ? g_qh : (z == 1) ? g_kh : g_vh;
    __nv_bfloat16* dl = (z == 0) ? g_ql : (z == 1) ? g_kl : g_vl;
    float zscale = (z == 0) ? 0.125f : 1.0f;

    int tid = threadIdx.x;
    int wid = tid >> 5, lane = tid & 31;
    int wm = wid >> 1, wn = wid & 1;
    int lr = lane & 15, lc = lane >> 4;

    uint32_t sb = smem_u32(s8buf);
    uint32_t stage_sb[2] = { sb, sb + STAGE8_B };

    int acc1[2][8][4], acc2[2][8][4];
    #pragma unroll
    for (int i = 0; i < 2; i++)
        #pragma unroll
        for (int j = 0; j < 8; j++) {
            acc1[i][j][0] = acc1[i][j][1] = acc1[i][j][2] = acc1[i][j][3] = 0;
            acc2[i][j][0] = acc2[i][j][1] = acc2[i][j][2] = acc2[i][j][3] = 0;
        }

    issue_stage8(xh, xl, wh, wl, m0, n0, 0, stage_sb[0], tid);
    CP_COMMIT();

    for (int kt = 0; kt < DM / 32; kt++) {
        int s = kt & 1;
        if (kt < DM / 32 - 1) {
            issue_stage8(xh, xl, wh, wl, m0, n0, kt + 1, stage_sb[s ^ 1], tid);
            CP_COMMIT();
            CP_WAIT1();
        } else {
            CP_WAIT0();
        }
        __syncthreads();

        uint32_t ab = stage_sb[s];
        uint32_t ahf[2][4], alf[2][4];
        #pragma unroll
        for (int mi = 0; mi < 2; mi++) {
            uint32_t off = (uint32_t)((wm * 32 + mi * 16 + lr) * RSB + lc * 16);
            LDSM4(ahf[mi], ab + I_XH + off);
            LDSM4(alf[mi], ab + I_XL + off);
        }
        #pragma unroll
        for (int ni = 0; ni < 4; ni++) {
            uint32_t bh[4], bl[4];
            uint32_t off = (uint32_t)((wn * 64 + ni * 16 + lr) * RSB + lc * 16);
            LDSM4(bh, ab + I_WH + off);
            LDSM4(bl, ab + I_WL + off);
            #pragma unroll
            for (int mi = 0; mi < 2; mi++)
                #pragma unroll
                for (int hf = 0; hf < 2; hf++)
                    IMMA16832(acc1[mi][ni * 2 + hf], ahf[mi], bh[hf], bh[hf + 2]);
            #pragma unroll
            for (int mi = 0; mi < 2; mi++)
                #pragma unroll
                for (int hf = 0; hf < 2; hf++)
                    IMMA16832(acc2[mi][ni * 2 + hf], ahf[mi], bl[hf], bl[hf + 2]);
            #pragma unroll
            for (int mi = 0; mi < 2; mi++)
                #pragma unroll
                for (int hf = 0; hf < 2; hf++)
                    IMMA16832(acc2[mi][ni * 2 + hf], alf[mi], bh[hf], bh[hf + 2]);
        }
        __syncthreads();
    }

    // epilogue: y = sx*sw*(acc1*16384 + acc2*128); write split-bf16 head-major
    int gr = lane >> 2, c2 = (lane & 3) * 2;
    const float* sxp = g_sqx + (size_t)z * MT + m0 + wm * 32;
    const float* swp = g_sqw + (size_t)z * DM + n0 + wn * 64;
    int h = (n0 + wn * 64) >> 6;
    #pragma unroll
    for (int mi = 0; mi < 2; mi++) {
        int mrow = wm * 32 + mi * 16 + gr;
        float s0 = sxp[mi * 16 + gr] * zscale;
        float s1 = sxp[mi * 16 + gr + 8] * zscale;
        int m = m0 + mrow;
        int bb = m >> 11, t = m & (NW - 1);
        size_t base = ((size_t)(bb * NH + h) * NW + t) * DK;
        #pragma unroll
        for (int nj = 0; nj < 8; nj++) {
            int d = nj * 8 + c2;
            float t0 = swp[d], t1 = swp[d + 1];
            float y00 = s0 * t0 * ((float)acc1[mi][nj][0] * 16384.f + (float)acc2[mi][nj][0] * 128.f);
            float y01 = s0 * t1 * ((float)acc1[mi][nj][1] * 16384.f + (float)acc2[mi][nj][1] * 128.f);
            float y10 = s1 * t0 * ((float)acc1[mi][nj][2] * 16384.f + (float)acc2[mi][nj][2] * 128.f);
            float y11 = s1 * t1 * ((float)acc1[mi][nj][3] * 16384.f + (float)acc2[mi][nj][3] * 128.f);
            uint32_t hp, lp;
            PACK_BF16X2(hp, y00, y01);
            float f0 = __uint_as_float(hp << 16), f1 = __uint_as_float(hp & 0xffff0000u);
            PACK_BF16X2(lp, y00 - f0, y01 - f1);
            *(uint32_t*)(dh + base + d) = hp;
            *(uint32_t*)(dl + base + d) = lp;
            PACK_BF16X2(hp, y10, y11);
            f0 = __uint_as_float(hp << 16); f1 = __uint_as_float(hp & 0xffff0000u);
            PACK_BF16X2(lp, y10 - f0, y11 - f1);
            *(uint32_t*)(dh + base + 8 * DK + d) = hp;
            *(uint32_t*)(dl + base + 8 * DK + d) = lp;
        }
    }
}

// ============================================================
// bf16 GEMM mainloop (out_mma only; R8/R11 proven)
// ============================================================
__device__ __forceinline__ void issue_stage(
    const __nv_bfloat16* __restrict__ xh, const __nv_bfloat16* __restrict__ xl,
    const __nv_bfloat16* __restrict__ wh, const __nv_bfloat16* __restrict__ wl,
    int m0, int n0, int kt, uint32_t stage_sb, int tid)
{
    #pragma unroll
    for (int t = 0; t < 8; t++) {
        int tile = t >> 1;
        int rem = tid + (t & 1) * 256;
        int row = rem >> 2, cq = rem & 3;
        const __nv_bfloat16* base = (tile == 0) ? xh : (tile == 1) ? xl
                                   : (tile == 2) ? wh : wl;
        int rb = (tile < 2) ? m0 : n0;
        size_t g = (size_t)(rb + row) * DM + kt * BKC + cq * 8;
        uint32_t sa = stage_sb + (uint32_t)(tile * 5120 + row * RS + cq * 8) * 2;
        CP_ASYNC16(sa, base + g);
    }
}

__device__ __forceinline__ void mma_mainloop(
    const __nv_bfloat16* __restrict__ xh, const __nv_bfloat16* __restrict__ xl,
    const __nv_bfloat16* __restrict__ wh, const __nv_bfloat16* __restrict__ wl,
    int m0, int n0, __nv_bfloat16* sbuf, float acc[2][8][4])
{
    int tid = threadIdx.x;
    int wid = tid >> 5, lane = tid & 31;
    int wm = wid >> 1, wn = wid & 1;
    int lr = lane & 15, lc = lane >> 4;

    uint32_t sb = smem_u32(sbuf);
    uint32_t stage_sb[2] = { sb, sb + (uint32_t)STAGE_EL * 2 };

    issue_stage(xh, xl, wh, wl, m0, n0, 0, stage_sb[0], tid);
    CP_COMMIT();

    for (int kt = 0; kt < DM / BKC; kt++) {
        int s = kt & 1;
        if (kt < DM / BKC - 1) {
            issue_stage(xh, xl, wh, wl, m0, n0, kt + 1, stage_sb[s ^ 1], tid);
            CP_COMMIT();
            CP_WAIT1();
        } else {
            CP_WAIT0();
        }
        __syncthreads();

        uint32_t ab = stage_sb[s];
        #pragma unroll
        for (int kk = 0; kk < BKC; kk += 16) {
            uint32_t ah[2][4], al[2][4];
            #pragma unroll
            for (int mi = 0; mi < 2; mi++) {
                uint32_t off = (uint32_t)((wm * 32 + mi * 16 + lr) * RS + kk + lc * 8) * 2;
                LDSM4(ah[mi], ab + XH_OFF * 2 + off);
                LDSM4(al[mi], ab + XL_OFF * 2 + off);
            }
            #pragma unroll
            for (int ni = 0; ni < 4; ni++) {
                uint32_t bh[4], bl[4];
                uint32_t off = (uint32_t)((wn * 64 + ni * 16 + lr) * RS + kk + lc * 8) * 2;
                LDSM4(bh, ab + WH_OFF * 2 + off);
                LDSM4(bl, ab + WL_OFF * 2 + off);
                #pragma unroll
                for (int mi = 0; mi < 2; mi++)
                    #pragma unroll
                    for (int hf = 0; hf < 2; hf++)
                        MMA16816(acc[mi][ni * 2 + hf], ah[mi], bh[hf], bh[hf + 2]);
                #pragma unroll
                for (int mi = 0; mi < 2; mi++)
                    #pragma unroll
                    for (int hf = 0; hf < 2; hf++)
                        MMA16816(acc[mi][ni * 2 + hf], ah[mi], bl[hf], bl[hf + 2]);
                #pragma unroll
                for (int mi = 0; mi < 2; mi++)
                    #pragma unroll
                    for (int hf = 0; hf < 2; hf++)
                        MMA16816(acc[mi][ni * 2 + hf], al[mi], bh[hf], bh[hf + 2]);
            }
        }
        __syncthreads();
    }
}

// ============================================================
// Output GEMM (bf16 3-term): attn @ Wo^T
// ============================================================
__global__ void __launch_bounds__(256, 2) out_mma_kernel(float* __restrict__ out) {
    extern __shared__ __nv_bfloat16 sbuf[];
    int m0 = blockIdx.y * 128, n0 = blockIdx.x * 128;

    float acc[2][8][4];
    #pragma unroll
    for (int i = 0; i < 2; i++)
        #pragma unroll
        for (int j = 0; j < 8; j++)
            acc[i][j][0] = acc[i][j][1] = acc[i][j][2] = acc[i][j][3] = 0.f;

    mma_mainloop(g_xh, g_xl, g_wh, g_wl, m0, n0, sbuf, acc);

    int tid = threadIdx.x, wid = tid >> 5, lane = tid & 31;
    int wm = wid >> 1, wn = wid & 1;
    #pragma unroll
    for (int mi = 0; mi < 2; mi++)
        #pragma unroll
        for (int nj = 0; nj < 8; nj++) {
            int n = n0 + wn * 64 + nj * 8 + (lane & 3) * 2;
            int m = m0 + wm * 32 + mi * 16 + (lane >> 2);
            *(float2*)(out + (size_t)m * DM + n) = make_float2(acc[mi][nj][0], acc[mi][nj][1]);
            *(float2*)(out + (size_t)(m + 8) * DM + n) = make_float2(acc[mi][nj][2], acc[mi][nj][3]);
        }
}

// ============================================================
// Flash attention (R11 best): 256 threads, 8 warps, 16 q/warp, 2 CTAs/SM
// ============================================================
__device__ __forceinline__ void flash_issue(
    const __nv_bfloat16* __restrict__ kh, const __nv_bfloat16* __restrict__ kl,
    const __nv_bfloat16* __restrict__ vh, const __nv_bfloat16* __restrict__ vl,
    int kt, uint32_t stage_sb, int tid)
{
    const __nv_bfloat16* gb[4] = { kh, kl, vh, vl };
    #pragma unroll
    for (int t = 0; t < 8; t++) {
        int tile = t >> 1;
        int rem = tid + (t & 1) * 256;
        int row = rem >> 3, cq = rem & 7;
        const __nv_bfloat16* g = gb[tile] + (size_t)(kt * 64 + row) * DK + cq * 8;
        uint32_t sa = stage_sb + (uint32_t)(tile * FTS + row * FRS + cq * 8) * 2;
        CP_ASYNC16(sa, g);
    }
}

__global__ void __launch_bounds__(256, 2) flash_mma_kernel() {
    extern __shared__ __nv_bfloat16 fsm[];
    int b = blockIdx.z, h = blockIdx.y, q0 = blockIdx.x * 128;
    int tid = threadIdx.x, wid = tid >> 5, lane = tid & 31;
    int lr = lane & 15, lc = lane >> 4;
    int gr = lane >> 2, c = lane & 3;

    size_t hb = (size_t)(b * NH + h) * NW * DK;
    const __nv_bfloat16* kh = g_kh + hb;
    const __nv_bfloat16* kl = g_kl + hb;
    const __nv_bfloat16* vh = g_vh + hb;
    const __nv_bfloat16* vl = g_vl + hb;
    const __nv_bfloat16* qh = g_qh + hb + (size_t)q0 * DK;
    const __nv_bfloat16* ql = g_ql + hb + (size_t)q0 * DK;

    uint32_t qhf[4][4];
    #pragma unroll
    for (int kc = 0; kc < 4; kc++) {
        int r0 = wid * 16 + gr, col = kc * 16 + 2 * c;
        qhf[kc][0] = *(const uint32_t*)(qh + (size_t)r0 * DK + col);
        qhf[kc][1] = *(const uint32_t*)(qh + (size_t)(r0 + 8) * DK + col);
        qhf[kc][2] = *(const uint32_t*)(qh + (size_t)r0 * DK + col + 8);
        qhf[kc][3] = *(const uint32_t*)(qh + (size_t)(r0 + 8) * DK + col + 8);
    }

    float oacc[8][4];
    #pragma unroll
    for (int j = 0; j < 8; j++)
        oacc[j][0] = oacc[j][1] = oacc[j][2] = oacc[j][3] = 0.f;
    float m0 = -INFINITY, m1 = -INFINITY, l0 = 0.f, l1 = 0.f;

    uint32_t sb = smem_u32(fsm);
    flash_issue(kh, kl, vh, vl, 0, sb, tid);
    CP_COMMIT();

    for (int kt = 0; kt < NW / 64; kt++) {
        int s = kt & 1;
        uint32_t ss = sb + (uint32_t)(s * FSTAGE) * 2;
        if (kt < NW / 64 - 1) {
            flash_issue(kh, kl, vh, vl, kt + 1, sb + (uint32_t)((s ^ 1) * FSTAGE) * 2, tid);
            CP_COMMIT();
            CP_WAIT1();
        } else {
            CP_WAIT0();
        }
        __syncthreads();

        const unsigned* mb0 = g_mb + (size_t)(b * NW + q0 + wid * 16 + gr) * MWPR + kt * 2;
        unsigned mw00 = mb0[0], mw01 = mb0[1];
        unsigned mw10 = mb0[8 * MWPR], mw11 = mb0[8 * MWPR + 1];

        float sacc[8][4];
        #pragma unroll
        for (int j = 0; j < 8; j++)
            sacc[j][0] = sacc[j][1] = sacc[j][2] = sacc[j][3] = 0.f;

        #pragma unroll
        for (int kc = 0; kc < 4; kc++) {
            uint32_t qlf[4];
            {
                int r0 = wid * 16 + gr, col = kc * 16 + 2 * c;
                qlf[0] = *(const uint32_t*)(ql + (size_t)r0 * DK + col);
                qlf[1] = *(const uint32_t*)(ql + (size_t)(r0 + 8) * DK + col);
                qlf[2] = *(const uint32_t*)(ql + (size_t)r0 * DK + col + 8);
                qlf[3] = *(const uint32_t*)(ql + (size_t)(r0 + 8) * DK + col + 8);
            }
            #pragma unroll
            for (int g = 0; g < 4; g++) {
                uint32_t khf[4], klf[4];
                uint32_t off = (uint32_t)((g * 16 + lr) * FRS + kc * 16 + lc * 8) * 2;
                LDSM4(khf, ss + off);
                LDSM4(klf, ss + (uint32_t)FTS * 2 + off);
                #pragma unroll
                for (int hf = 0; hf < 2; hf++)
                    MMA16816(sacc[2 * g + hf], qhf[kc], khf[hf], khf[hf + 2]);
                #pragma unroll
                for (int hf = 0; hf < 2; hf++)
                    MMA16816(sacc[2 * g + hf], qhf[kc], klf[hf], klf[hf + 2]);
                #pragma unroll
                for (int hf = 0; hf < 2; hf++)
                    MMA16816(sacc[2 * g + hf], qlf,     khf[hf], khf[hf + 2]);
            }
        }

        #pragma unroll
        for (int j = 0; j < 8; j++) {
            unsigned wr0 = (j < 4) ? mw00 : mw01;
            unsigned wr1 = (j < 4) ? mw10 : mw11;
            int bit = (8 * j + 2 * c) & 31;
            if (!((wr0 >> bit) & 1u))       sacc[j][0] = -1e9f;
            if (!((wr0 >> (bit + 1)) & 1u)) sacc[j][1] = -1e9f;
            if (!((wr1 >> bit) & 1u))       sacc[j][2] = -1e9f;
            if (!((wr1 >> (bit + 1)) & 1u)) sacc[j][3] = -1e9f;
        }

        float mx0 = -INFINITY, mx1 = -INFINITY;
        #pragma unroll
        for (int j = 0; j < 8; j++) {
            mx0 = fmaxf(mx0, fmaxf(sacc[j][0], sacc[j][1]));
            mx1 = fmaxf(mx1, fmaxf(sacc[j][2], sacc[j][3]));
        }
        mx0 = fmaxf(mx0, __shfl_xor_sync(0xffffffffu, mx0, 1));
        mx0 = fmaxf(mx0, __shfl_xor_sync(0xffffffffu, mx0, 2));
        mx1 = fmaxf(mx1, __shfl_xor_sync(0xffffffffu, mx1, 1));
        mx1 = fmaxf(mx1, __shfl_xor_sync(0xffffffffu, mx1, 2));

        float nm0 = fmaxf(m0, mx0), nm1 = fmaxf(m1, mx1);
        float sc0 = __expf(m0 - nm0), sc1 = __expf(m1 - nm1);
        float rs0 = 0.f, rs1 = 0.f;
        #pragma unroll
        for (int j = 0; j < 8; j++) {
            sacc[j][0] = __expf(sacc[j][0] - nm0);
            sacc[j][1] = __expf(sacc[j][1] - nm0);
            sacc[j][2] = __expf(sacc[j][2] - nm1);
            sacc[j][3] = __expf(sacc[j][3] - nm1);
            rs0 += sacc[j][0] + sacc[j][1];
            rs1 += sacc[j][2] + sacc[j][3];
        }
        rs0 += __shfl_xor_sync(0xffffffffu, rs0, 1);
        rs0 += __shfl_xor_sync(0xffffffffu, rs0, 2);
        rs1 += __shfl_xor_sync(0xffffffffu, rs1, 1);
        rs1 += __shfl_xor_sync(0xffffffffu, rs1, 2);
        m0 = nm0; m1 = nm1;
        l0 = l0 * sc0 + rs0;
        l1 = l1 * sc1 + rs1;
        #pragma unroll
        for (int j = 0; j < 8; j++) {
            oacc[j][0] *= sc0; oacc[j][1] *= sc0;
            oacc[j][2] *= sc1; oacc[j][3] *= sc1;
        }

        uint32_t phf[4][4], plf[4][4];
        #pragma unroll
        for (int kc = 0; kc < 4; kc++) {
            #pragma unroll
            for (int q = 0; q < 4; q++) {
                int jt = 2 * kc + (q >> 1);
                float p0 = sacc[jt][(q & 1) ? 2 : 0];
                float p1 = sacc[jt][(q & 1) ? 3 : 1];
                uint32_t hp, lp;
                PACK_BF16X2(hp, p0, p1);
                float f0 = __uint_as_float(hp << 16);
                float f1 = __uint_as_float(hp & 0xffff0000u);
                PACK_BF16X2(lp, p0 - f0, p1 - f1);
                phf[kc][q] = hp; plf[kc][q] = lp;
            }
        }

        #pragma unroll
        for (int kc = 0; kc < 4; kc++) {
            #pragma unroll
            for (int dg = 0; dg < 4; dg++) {
                uint32_t vhf[4], vlf[4];
                uint32_t off = (uint32_t)((kc * 16 + lr) * FRS + dg * 16 + lc * 8) * 2;
                LDSM4T(vhf, ss + (uint32_t)(2 * FTS) * 2 + off);
                LDSM4T(vlf, ss + (uint32_t)(3 * FTS) * 2 + off);
                MMA16816(oacc[2 * dg],     phf[kc], vhf[0], vhf[1]);
                MMA16816(oacc[2 * dg + 1], phf[kc], vhf[2], vhf[3]);
                MMA16816(oacc[2 * dg],     plf[kc], vhf[0], vhf[1]);
                MMA16816(oacc[2 * dg + 1], plf[kc], vhf[2], vhf[3]);
                MMA16816(oacc[2 * dg],     phf[kc], vlf[0], vlf[1]);
                MMA16816(oacc[2 * dg + 1], phf[kc], vlf[2], vlf[3]);
            }
        }
        __syncthreads();
    }

    float inv0 = 1.f / l0, inv1 = 1.f / l1;
    int row0 = q0 + wid * 16 + gr;
    size_t base0 = ((size_t)b * NW + row0) * DM + h * DK;
    #pragma unroll
    for (int j = 0; j < 8; j++) {
        int d = 8 * j + 2 * c;
        float v0 = oacc[j][0] * inv0, v1 = oacc[j][1] * inv0;
        uint32_t hp, lp;
        PACK_BF16X2(hp, v0, v1);
        float f0 = __uint_as_float(hp << 16), f1 = __uint_as_float(hp & 0xffff0000u);
        PACK_BF16X2(lp, v0 - f0, v1 - f1);
        *(uint32_t*)((__nv_bfloat16*)g_xh + base0 + d) = hp;
        *(uint32_t*)((__nv_bfloat16*)g_xl + base0 + d) = lp;
        v0 = oacc[j][2] * inv1; v1 = oacc[j][3] * inv1;
        PACK_BF16X2(hp, v0, v1);
        f0 = __uint_as_float(hp << 16); f1 = __uint_as_float(hp & 0xffff0000u);
        PACK_BF16X2(lp, v0 - f0, v1 - f1);
        *(uint32_t*)((__nv_bfloat16*)g_xh + base0 + 8 * DM + d) = hp;
        *(uint32_t*)((__nv_bfloat16*)g_xl + base0 + 8 * DM + d) = lp;
    }
}

// ============================================================
extern "C" void kernel_launch(void* const* d_in, const int* in_sizes, int n_in,
                              void* d_out, int out_size) {
    const float* Q  = (const float*)d_in[0];
    const float* K  = (const float*)d_in[1];
    const float* V  = (const float*)d_in[2];
    const int* mask = (const int*)d_in[3];
    const float* Wq = (const float*)d_in[4];
    const float* Wk = (const float*)d_in[5];
    const float* Wv = (const float*)d_in[6];
    const float* Wo = (const float*)d_in[7];
    float* out = (float*)d_out;

    static int attr_done = 0;
    if (!attr_done) {
        cudaFuncSetAttribute(proj_imma_kernel, cudaFuncAttributeMaxDynamicSharedMemorySize, SMEM_I8);
        cudaFuncSetAttribute(out_mma_kernel, cudaFuncAttributeMaxDynamicSharedMemorySize, SMEM_MMA);
        cudaFuncSetAttribute(flash_mma_kernel, cudaFuncAttributeMaxDynamicSharedMemorySize, SMEM_FLASH);
        attr_done = 1;
    }

    prep_kernel<<<PREP_BLKS, 256>>>(mask, Q, K, V, Wq, Wk, Wv, Wo);
    proj_imma_kernel<<<dim3(DM / 128, MT / 128, 3), 256, SMEM_I8>>>();
    flash_mma_kernel<<<dim3(NW / 128, NH, NB), 256, SMEM_FLASH>>>();
    out_mma_kernel<<<dim3(DM / 128, MT / 128), 256, SMEM_MMA>>>(out);
}

// round 13
// speedup vs baseline: 1.5852x; 1.5852x over previous
#include <cuda_runtime.h>
#include <cuda_bf16.h>
#include <cstdint>
#include <math.h>

#define NB 4
#define NW 2048
#define DM 1024
#define NH 16
#define DK 64
#define MT (NB*NW)
#define MWPR (NW/32)

// ---------------- device scratch ----------------
__device__ unsigned g_mb[NB*NW*MWPR];
__device__ __nv_bfloat16 g_xh[3u*MT*DM];   // hi of Q,K,V inputs (slot 0 reused for attn out)
__device__ __nv_bfloat16 g_xl[3u*MT*DM];
__device__ __nv_bfloat16 g_wh[4u*DM*DM];
__device__ __nv_bfloat16 g_wl[4u*DM*DM];
__device__ __nv_bfloat16 g_qh[NB*NH*NW*DK];
__device__ __nv_bfloat16 g_ql[NB*NH*NW*DK];
__device__ __nv_bfloat16 g_kh[NB*NH*NW*DK];
__device__ __nv_bfloat16 g_kl[NB*NH*NW*DK];
__device__ __nv_bfloat16 g_vh[NB*NH*NW*DK];
__device__ __nv_bfloat16 g_vl[NB*NH*NW*DK];

// ---------------- PTX helpers ----------------
__device__ __forceinline__ uint32_t smem_u32(const void* p) {
    uint32_t a;
    asm("{ .reg .u64 t; cvta.to.shared.u64 t, %1; cvt.u32.u64 %0, t; }" : "=r"(a) : "l"(p));
    return a;
}
#define CP_ASYNC16(sa, g) \
    asm volatile("cp.async.cg.shared.global [%0], [%1], 16;" :: "r"(sa), "l"(g))
#define CP_COMMIT() asm volatile("cp.async.commit_group;" ::: "memory")
#define CP_WAIT1()  asm volatile("cp.async.wait_group 1;" ::: "memory")
#define CP_WAIT0()  asm volatile("cp.async.wait_group 0;" ::: "memory")

#define LDSM4(r, addr) \
    asm volatile("ldmatrix.sync.aligned.m8n8.x4.shared.b16 {%0,%1,%2,%3}, [%4];" \
        : "=r"((r)[0]), "=r"((r)[1]), "=r"((r)[2]), "=r"((r)[3]) : "r"(addr))
#define LDSM4T(r, addr) \
    asm volatile("ldmatrix.sync.aligned.m8n8.x4.trans.shared.b16 {%0,%1,%2,%3}, [%4];" \
        : "=r"((r)[0]), "=r"((r)[1]), "=r"((r)[2]), "=r"((r)[3]) : "r"(addr))

#define MMA16816(d, a, b0, b1) \
    asm volatile("mma.sync.aligned.m16n8k16.row.col.f32.bf16.bf16.f32 " \
        "{%0,%1,%2,%3}, {%4,%5,%6,%7}, {%8,%9}, {%0,%1,%2,%3};" \
        : "+f"((d)[0]), "+f"((d)[1]), "+f"((d)[2]), "+f"((d)[3]) \
        : "r"((a)[0]), "r"((a)[1]), "r"((a)[2]), "r"((a)[3]), "r"(b0), "r"(b1))

#define PACK_BF16X2(r, lo, hi) \
    asm("cvt.rn.bf16x2.f32 %0, %1, %2;" : "=r"(r) : "f"(hi), "f"(lo))

// ---- GEMM smem geometry (R8/R11 proven): CTA 128x128, 8 warps (4x2), warp 32x64, 2 stages ----
#define BKC    32
#define RS     40
#define XH_OFF 0
#define XL_OFF 5120
#define WH_OFF 10240
#define WL_OFF 15360
#define STAGE_EL 20480
#define SMEM_MMA (2*STAGE_EL*2)         // 81920 B -> 2 CTAs/SM

// ---- flash smem geometry ----
#define FRS    72
#define FTS    (64*FRS)
#define FSTAGE (4*FTS)
#define SMEM_FLASH (2*FSTAGE*2)          // 73728 B

#define NX_ELEMS  ((size_t)MT*DM)
#define NWT_ELEMS ((size_t)DM*DM)
#define PACK_BLKS  ((NB*NW*NW)/1024)     // 16384 (int4 loads: 1024 elems/block)
#define CONVX_BLKS ((3*MT*DM)/1024)      // 24576
#define CONVW_BLKS ((4*DM*DM)/1024)      // 4096
#define PREP_BLKS  (PACK_BLKS + CONVX_BLKS + CONVW_BLKS)

// ============================================================
// prep: mask pack (vectorized int4) + fp32->split bf16 conversions
// ============================================================
__device__ __forceinline__ void conv4_store(const float* __restrict__ src, size_t off,
                                            __nv_bfloat16* __restrict__ hi,
                                            __nv_bfloat16* __restrict__ lo, size_t i) {
    float4 v = *(const float4*)(src + off);
    __nv_bfloat16 h0 = __float2bfloat16(v.x), h1 = __float2bfloat16(v.y);
    __nv_bfloat16 h2 = __float2bfloat16(v.z), h3 = __float2bfloat16(v.w);
    __nv_bfloat16 l0 = __float2bfloat16(v.x - __bfloat162float(h0));
    __nv_bfloat16 l1 = __float2bfloat16(v.y - __bfloat162float(h1));
    __nv_bfloat16 l2 = __float2bfloat16(v.z - __bfloat162float(h2));
    __nv_bfloat16 l3 = __float2bfloat16(v.w - __bfloat162float(h3));
    ((__nv_bfloat162*)(hi + i))[0] = __nv_bfloat162(h0, h1);
    ((__nv_bfloat162*)(hi + i))[1] = __nv_bfloat162(h2, h3);
    ((__nv_bfloat162*)(lo + i))[0] = __nv_bfloat162(l0, l1);
    ((__nv_bfloat162*)(lo + i))[1] = __nv_bfloat162(l2, l3);
}

__global__ void __launch_bounds__(256) prep_kernel(
    const int* __restrict__ mask,
    const float* __restrict__ Q, const float* __restrict__ K, const float* __restrict__ V,
    const float* __restrict__ Wq, const float* __restrict__ Wk,
    const float* __restrict__ Wv, const float* __restrict__ Wo)
{
    __shared__ uint8_t nib[256];
    int bid = blockIdx.x, tid = threadIdx.x;
    if (bid < PACK_BLKS) {
        // 16B vectorized mask pack: block covers 1024 int32 -> 32 words
        const int4* mp = (const int4*)mask;
        int4 v = mp[(size_t)bid * 256 + tid];
        unsigned n = (unsigned)(v.x != 0) | ((unsigned)(v.y != 0) << 1)
                   | ((unsigned)(v.z != 0) << 2) | ((unsigned)(v.w != 0) << 3);
        nib[tid] = (uint8_t)n;
        __syncthreads();
        if (tid < 32) {
            const uint8_t* p = nib + tid * 8;
            unsigned w = 0;
            #pragma unroll
            for (int i = 0; i < 8; i++) w |= ((unsigned)p[i]) << (4 * i);
            g_mb[bid * 32 + tid] = w;
        }
        return;
    }
    bid -= PACK_BLKS;
    if (bid < CONVX_BLKS) {
        size_t i = ((size_t)bid * 256 + tid) * 4;
        const float* src; size_t off;
        if (i < NX_ELEMS)            { src = Q; off = i; }
        else if (i < 2 * NX_ELEMS)   { src = K; off = i - NX_ELEMS; }
        else                         { src = V; off = i - 2 * NX_ELEMS; }
        conv4_store(src, off, g_xh, g_xl, i);
        return;
    }
    bid -= CONVX_BLKS;
    {
        size_t i = ((size_t)bid * 256 + tid) * 4;
        const float* src; size_t off;
        if (i < NWT_ELEMS)            { src = Wq; off = i; }
        else if (i < 2 * NWT_ELEMS)   { src = Wk; off = i - NWT_ELEMS; }
        else if (i < 3 * NWT_ELEMS)   { src = Wv; off = i - 2 * NWT_ELEMS; }
        else                          { src = Wo; off = i - 3 * NWT_ELEMS; }
        conv4_store(src, off, g_wh, g_wl, i);
    }
}

// ============================================================
// GEMM: C[128x128] = X[m0:+128,:] * W[n0:+128,:]^T, split-bf16 3-term
// 256 threads, 8 warps (4x2), warp tile 32x64 (R11 proven)
// ============================================================
__device__ __forceinline__ void issue_stage(
    const __nv_bfloat16* __restrict__ xh, const __nv_bfloat16* __restrict__ xl,
    const __nv_bfloat16* __restrict__ wh, const __nv_bfloat16* __restrict__ wl,
    int m0, int n0, int kt, uint32_t stage_sb, int tid)
{
    #pragma unroll
    for (int t = 0; t < 8; t++) {
        int tile = t >> 1;                   // 0=Xh 1=Xl 2=Wh 3=Wl
        int rem = tid + (t & 1) * 256;       // 0..511
        int row = rem >> 2, cq = rem & 3;
        const __nv_bfloat16* base = (tile == 0) ? xh : (tile == 1) ? xl
                                   : (tile == 2) ? wh : wl;
        int rb = (tile < 2) ? m0 : n0;
        size_t g = (size_t)(rb + row) * DM + kt * BKC + cq * 8;
        uint32_t sa = stage_sb + (uint32_t)(tile * 5120 + row * RS + cq * 8) * 2;
        CP_ASYNC16(sa, base + g);
    }
}

__device__ __forceinline__ void mma_mainloop(
    const __nv_bfloat16* __restrict__ xh, const __nv_bfloat16* __restrict__ xl,
    const __nv_bfloat16* __restrict__ wh, const __nv_bfloat16* __restrict__ wl,
    int m0, int n0, __nv_bfloat16* sbuf, float acc[2][8][4])
{
    int tid = threadIdx.x;
    int wid = tid >> 5, lane = tid & 31;
    int wm = wid >> 1, wn = wid & 1;
    int lr = lane & 15, lc = lane >> 4;

    uint32_t sb = smem_u32(sbuf);
    uint32_t stage_sb[2] = { sb, sb + (uint32_t)STAGE_EL * 2 };

    issue_stage(xh, xl, wh, wl, m0, n0, 0, stage_sb[0], tid);
    CP_COMMIT();

    for (int kt = 0; kt < DM / BKC; kt++) {
        int s = kt & 1;
        if (kt < DM / BKC - 1) {
            issue_stage(xh, xl, wh, wl, m0, n0, kt + 1, stage_sb[s ^ 1], tid);
            CP_COMMIT();
            CP_WAIT1();
        } else {
            CP_WAIT0();
        }
        __syncthreads();

        uint32_t ab = stage_sb[s];
        #pragma unroll
        for (int kk = 0; kk < BKC; kk += 16) {
            uint32_t ah[2][4], al[2][4];
            #pragma unroll
            for (int mi = 0; mi < 2; mi++) {
                uint32_t off = (uint32_t)((wm * 32 + mi * 16 + lr) * RS + kk + lc * 8) * 2;
                LDSM4(ah[mi], ab + XH_OFF * 2 + off);
                LDSM4(al[mi], ab + XL_OFF * 2 + off);
            }
            #pragma unroll
            for (int ni = 0; ni < 4; ni++) {
                uint32_t bh[4], bl[4];
                uint32_t off = (uint32_t)((wn * 64 + ni * 16 + lr) * RS + kk + lc * 8) * 2;
                LDSM4(bh, ab + WH_OFF * 2 + off);
                LDSM4(bl, ab + WL_OFF * 2 + off);
                #pragma unroll
                for (int mi = 0; mi < 2; mi++)
                    #pragma unroll
                    for (int hf = 0; hf < 2; hf++)
                        MMA16816(acc[mi][ni * 2 + hf], ah[mi], bh[hf], bh[hf + 2]);
                #pragma unroll
                for (int mi = 0; mi < 2; mi++)
                    #pragma unroll
                    for (int hf = 0; hf < 2; hf++)
                        MMA16816(acc[mi][ni * 2 + hf], ah[mi], bl[hf], bl[hf + 2]);
                #pragma unroll
                for (int mi = 0; mi < 2; mi++)
                    #pragma unroll
                    for (int hf = 0; hf < 2; hf++)
                        MMA16816(acc[mi][ni * 2 + hf], al[mi], bh[hf], bh[hf + 2]);
            }
        }
        __syncthreads();
    }
}

// ============================================================
// Projection GEMM: epilogue writes split-bf16 head-major q/k/v
// ============================================================
__global__ void __launch_bounds__(256, 2) proj_mma_kernel() {
    extern __shared__ __nv_bfloat16 sbuf[];
    int z = blockIdx.z;
    int m0 = blockIdx.y * 128, n0 = blockIdx.x * 128;
    const __nv_bfloat16* xh = g_xh + (size_t)z * MT * DM;
    const __nv_bfloat16* xl = g_xl + (size_t)z * MT * DM;
    const __nv_bfloat16* wh = g_wh + (size_t)z * DM * DM;
    const __nv_bfloat16* wl = g_wl + (size_t)z * DM * DM;
    __nv_bfloat16* dh = (z == 0) ? g_qh : (z == 1) ? g_kh : g_vh;
    __nv_bfloat16* dl = (z == 0) ? g_ql : (z == 1) ? g_kl : g_vl;
    float scale = (z == 0) ? 0.125f : 1.0f;

    float acc[2][8][4];
    #pragma unroll
    for (int i = 0; i < 2; i++)
        #pragma unroll
        for (int j = 0; j < 8; j++)
            acc[i][j][0] = acc[i][j][1] = acc[i][j][2] = acc[i][j][3] = 0.f;

    mma_mainloop(xh, xl, wh, wl, m0, n0, sbuf, acc);

    int tid = threadIdx.x, wid = tid >> 5, lane = tid & 31;
    int wm = wid >> 1, wn = wid & 1;
    int h = (n0 + wn * 64) >> 6;             // warp's 64-wide n-band = one head
    #pragma unroll
    for (int mi = 0; mi < 2; mi++)
        #pragma unroll
        for (int nj = 0; nj < 8; nj++) {
            int d = nj * 8 + (lane & 3) * 2;
            int m = m0 + wm * 32 + mi * 16 + (lane >> 2);
            int bb = m >> 11, t = m & (NW - 1);
            size_t off = ((size_t)(bb * NH + h) * NW + t) * DK + d;
            float v0 = acc[mi][nj][0] * scale, v1 = acc[mi][nj][1] * scale;
            uint32_t hp, lp;
            PACK_BF16X2(hp, v0, v1);
            float f0 = __uint_as_float(hp << 16), f1 = __uint_as_float(hp & 0xffff0000u);
            PACK_BF16X2(lp, v0 - f0, v1 - f1);
            *(uint32_t*)(dh + off) = hp;
            *(uint32_t*)(dl + off) = lp;
            v0 = acc[mi][nj][2] * scale; v1 = acc[mi][nj][3] * scale;
            PACK_BF16X2(hp, v0, v1);
            f0 = __uint_as_float(hp << 16); f1 = __uint_as_float(hp & 0xffff0000u);
            PACK_BF16X2(lp, v0 - f0, v1 - f1);
            *(uint32_t*)(dh + off + 8 * DK) = hp;
            *(uint32_t*)(dl + off + 8 * DK) = lp;
        }
}

// ============================================================
// Output GEMM
// ============================================================
__global__ void __launch_bounds__(256, 2) out_mma_kernel(float* __restrict__ out) {
    extern __shared__ __nv_bfloat16 sbuf[];
    int m0 = blockIdx.y * 128, n0 = blockIdx.x * 128;
    const __nv_bfloat16* wh = g_wh + (size_t)3 * DM * DM;
    const __nv_bfloat16* wl = g_wl + (size_t)3 * DM * DM;

    float acc[2][8][4];
    #pragma unroll
    for (int i = 0; i < 2; i++)
        #pragma unroll
        for (int j = 0; j < 8; j++)
            acc[i][j][0] = acc[i][j][1] = acc[i][j][2] = acc[i][j][3] = 0.f;

    mma_mainloop(g_xh, g_xl, wh, wl, m0, n0, sbuf, acc);

    int tid = threadIdx.x, wid = tid >> 5, lane = tid & 31;
    int wm = wid >> 1, wn = wid & 1;
    #pragma unroll
    for (int mi = 0; mi < 2; mi++)
        #pragma unroll
        for (int nj = 0; nj < 8; nj++) {
            int n = n0 + wn * 64 + nj * 8 + (lane & 3) * 2;
            int m = m0 + wm * 32 + mi * 16 + (lane >> 2);
            *(float2*)(out + (size_t)m * DM + n) = make_float2(acc[mi][nj][0], acc[mi][nj][1]);
            *(float2*)(out + (size_t)(m + 8) * DM + n) = make_float2(acc[mi][nj][2], acc[mi][nj][3]);
        }
}

// ============================================================
// Flash attention (R11): 256 threads, 8 warps, 16 q/warp, 2 CTAs/SM
// ============================================================
__device__ __forceinline__ void flash_issue(
    const __nv_bfloat16* __restrict__ kh, const __nv_bfloat16* __restrict__ kl,
    const __nv_bfloat16* __restrict__ vh, const __nv_bfloat16* __restrict__ vl,
    int kt, uint32_t stage_sb, int tid)
{
    const __nv_bfloat16* gb[4] = { kh, kl, vh, vl };
    #pragma unroll
    for (int t = 0; t < 8; t++) {
        int tile = t >> 1;
        int rem = tid + (t & 1) * 256;
        int row = rem >> 3, cq = rem & 7;
        const __nv_bfloat16* g = gb[tile] + (size_t)(kt * 64 + row) * DK + cq * 8;
        uint32_t sa = stage_sb + (uint32_t)(tile * FTS + row * FRS + cq * 8) * 2;
        CP_ASYNC16(sa, g);
    }
}

__global__ void __launch_bounds__(256, 2) flash_mma_kernel() {
    extern __shared__ __nv_bfloat16 fsm[];
    int b = blockIdx.z, h = blockIdx.y, q0 = blockIdx.x * 128;
    int tid = threadIdx.x, wid = tid >> 5, lane = tid & 31;
    int lr = lane & 15, lc = lane >> 4;
    int gr = lane >> 2, c = lane & 3;

    size_t hb = (size_t)(b * NH + h) * NW * DK;
    const __nv_bfloat16* kh = g_kh + hb;
    const __nv_bfloat16* kl = g_kl + hb;
    const __nv_bfloat16* vh = g_vh + hb;
    const __nv_bfloat16* vl = g_vl + hb;
    const __nv_bfloat16* qh = g_qh + hb + (size_t)q0 * DK;
    const __nv_bfloat16* ql = g_ql + hb + (size_t)q0 * DK;

    uint32_t qhf[4][4];
    #pragma unroll
    for (int kc = 0; kc < 4; kc++) {
        int r0 = wid * 16 + gr, col = kc * 16 + 2 * c;
        qhf[kc][0] = *(const uint32_t*)(qh + (size_t)r0 * DK + col);
        qhf[kc][1] = *(const uint32_t*)(qh + (size_t)(r0 + 8) * DK + col);
        qhf[kc][2] = *(const uint32_t*)(qh + (size_t)r0 * DK + col + 8);
        qhf[kc][3] = *(const uint32_t*)(qh + (size_t)(r0 + 8) * DK + col + 8);
    }

    float oacc[8][4];
    #pragma unroll
    for (int j = 0; j < 8; j++)
        oacc[j][0] = oacc[j][1] = oacc[j][2] = oacc[j][3] = 0.f;
    float m0 = -INFINITY, m1 = -INFINITY, l0 = 0.f, l1 = 0.f;

    uint32_t sb = smem_u32(fsm);
    flash_issue(kh, kl, vh, vl, 0, sb, tid);
    CP_COMMIT();

    for (int kt = 0; kt < NW / 64; kt++) {
        int s = kt & 1;
        uint32_t ss = sb + (uint32_t)(s * FSTAGE) * 2;
        if (kt < NW / 64 - 1) {
            flash_issue(kh, kl, vh, vl, kt + 1, sb + (uint32_t)((s ^ 1) * FSTAGE) * 2, tid);
            CP_COMMIT();
            CP_WAIT1();
        } else {
            CP_WAIT0();
        }
        __syncthreads();

        const unsigned* mb0 = g_mb + (size_t)(b * NW + q0 + wid * 16 + gr) * MWPR + kt * 2;
        unsigned mw00 = mb0[0], mw01 = mb0[1];
        unsigned mw10 = mb0[8 * MWPR], mw11 = mb0[8 * MWPR + 1];

        float sacc[8][4];
        #pragma unroll
        for (int j = 0; j < 8; j++)
            sacc[j][0] = sacc[j][1] = sacc[j][2] = sacc[j][3] = 0.f;

        #pragma unroll
        for (int kc = 0; kc < 4; kc++) {
            uint32_t qlf[4];
            {
                int r0 = wid * 16 + gr, col = kc * 16 + 2 * c;
                qlf[0] = *(const uint32_t*)(ql + (size_t)r0 * DK + col);
                qlf[1] = *(const uint32_t*)(ql + (size_t)(r0 + 8) * DK + col);
                qlf[2] = *(const uint32_t*)(ql + (size_t)r0 * DK + col + 8);
                qlf[3] = *(const uint32_t*)(ql + (size_t)(r0 + 8) * DK + col + 8);
            }
            #pragma unroll
            for (int g = 0; g < 4; g++) {
                uint32_t khf[4], klf[4];
                uint32_t off = (uint32_t)((g * 16 + lr) * FRS + kc * 16 + lc * 8) * 2;
                LDSM4(khf, ss + off);
                LDSM4(klf, ss + (uint32_t)FTS * 2 + off);
                #pragma unroll
                for (int hf = 0; hf < 2; hf++)
                    MMA16816(sacc[2 * g + hf], qhf[kc], khf[hf], khf[hf + 2]);
                #pragma unroll
                for (int hf = 0; hf < 2; hf++)
                    MMA16816(sacc[2 * g + hf], qhf[kc], klf[hf], klf[hf + 2]);
                #pragma unroll
                for (int hf = 0; hf < 2; hf++)
                    MMA16816(sacc[2 * g + hf], qlf,     khf[hf], khf[hf + 2]);
            }
        }

        #pragma unroll
        for (int j = 0; j < 8; j++) {
            unsigned wr0 = (j < 4) ? mw00 : mw01;
            unsigned wr1 = (j < 4) ? mw10 : mw11;
            int bit = (8 * j + 2 * c) & 31;
            if (!((wr0 >> bit) & 1u))       sacc[j][0] = -1e9f;
            if (!((wr0 >> (bit + 1)) & 1u)) sacc[j][1] = -1e9f;
            if (!((wr1 >> bit) & 1u))       sacc[j][2] = -1e9f;
            if (!((wr1 >> (bit + 1)) & 1u)) sacc[j][3] = -1e9f;
        }

        float mx0 = -INFINITY, mx1 = -INFINITY;
        #pragma unroll
        for (int j = 0; j < 8; j++) {
            mx0 = fmaxf(mx0, fmaxf(sacc[j][0], sacc[j][1]));
            mx1 = fmaxf(mx1, fmaxf(sacc[j][2], sacc[j][3]));
        }
        mx0 = fmaxf(mx0, __shfl_xor_sync(0xffffffffu, mx0, 1));
        mx0 = fmaxf(mx0, __shfl_xor_sync(0xffffffffu, mx0, 2));
        mx1 = fmaxf(mx1, __shfl_xor_sync(0xffffffffu, mx1, 1));
        mx1 = fmaxf(mx1, __shfl_xor_sync(0xffffffffu, mx1, 2));

        float nm0 = fmaxf(m0, mx0), nm1 = fmaxf(m1, mx1);
        float sc0 = __expf(m0 - nm0), sc1 = __expf(m1 - nm1);
        float rs0 = 0.f, rs1 = 0.f;
        #pragma unroll
        for (int j = 0; j < 8; j++) {
            sacc[j][0] = __expf(sacc[j][0] - nm0);
            sacc[j][1] = __expf(sacc[j][1] - nm0);
            sacc[j][2] = __expf(sacc[j][2] - nm1);
            sacc[j][3] = __expf(sacc[j][3] - nm1);
            rs0 += sacc[j][0] + sacc[j][1];
            rs1 += sacc[j][2] + sacc[j][3];
        }
        rs0 += __shfl_xor_sync(0xffffffffu, rs0, 1);
        rs0 += __shfl_xor_sync(0xffffffffu, rs0, 2);
        rs1 += __shfl_xor_sync(0xffffffffu, rs1, 1);
        rs1 += __shfl_xor_sync(0xffffffffu, rs1, 2);
        m0 = nm0; m1 = nm1;
        l0 = l0 * sc0 + rs0;
        l1 = l1 * sc1 + rs1;
        #pragma unroll
        for (int j = 0; j < 8; j++) {
            oacc[j][0] *= sc0; oacc[j][1] *= sc0;
            oacc[j][2] *= sc1; oacc[j][3] *= sc1;
        }

        uint32_t phf[4][4], plf[4][4];
        #pragma unroll
        for (int kc = 0; kc < 4; kc++) {
            #pragma unroll
            for (int q = 0; q < 4; q++) {
                int jt = 2 * kc + (q >> 1);
                float p0 = sacc[jt][(q & 1) ? 2 : 0];
                float p1 = sacc[jt][(q & 1) ? 3 : 1];
                uint32_t hp, lp;
                PACK_BF16X2(hp, p0, p1);
                float f0 = __uint_as_float(hp << 16);
                float f1 = __uint_as_float(hp & 0xffff0000u);
                PACK_BF16X2(lp, p0 - f0, p1 - f1);
                phf[kc][q] = hp; plf[kc][q] = lp;
            }
        }

        #pragma unroll
        for (int kc = 0; kc < 4; kc++) {
            #pragma unroll
            for (int dg = 0; dg < 4; dg++) {
                uint32_t vhf[4], vlf[4];
                uint32_t off = (uint32_t)((kc * 16 + lr) * FRS + dg * 16 + lc * 8) * 2;
                LDSM4T(vhf, ss + (uint32_t)(2 * FTS) * 2 + off);
                LDSM4T(vlf, ss + (uint32_t)(3 * FTS) * 2 + off);
                MMA16816(oacc[2 * dg],     phf[kc], vhf[0], vhf[1]);
                MMA16816(oacc[2 * dg + 1], phf[kc], vhf[2], vhf[3]);
                MMA16816(oacc[2 * dg],     plf[kc], vhf[0], vhf[1]);
                MMA16816(oacc[2 * dg + 1], plf[kc], vhf[2], vhf[3]);
                MMA16816(oacc[2 * dg],     phf[kc], vlf[0], vlf[1]);
                MMA16816(oacc[2 * dg + 1], phf[kc], vlf[2], vlf[3]);
            }
        }
        __syncthreads();
    }

    float inv0 = 1.f / l0, inv1 = 1.f / l1;
    int row0 = q0 + wid * 16 + gr;
    size_t base0 = ((size_t)b * NW + row0) * DM + h * DK;
    #pragma unroll
    for (int j = 0; j < 8; j++) {
        int d = 8 * j + 2 * c;
        float v0 = oacc[j][0] * inv0, v1 = oacc[j][1] * inv0;
        uint32_t hp, lp;
        PACK_BF16X2(hp, v0, v1);
        float f0 = __uint_as_float(hp << 16), f1 = __uint_as_float(hp & 0xffff0000u);
        PACK_BF16X2(lp, v0 - f0, v1 - f1);
        *(uint32_t*)((__nv_bfloat16*)g_xh + base0 + d) = hp;
        *(uint32_t*)((__nv_bfloat16*)g_xl + base0 + d) = lp;
        v0 = oacc[j][2] * inv1; v1 = oacc[j][3] * inv1;
        PACK_BF16X2(hp, v0, v1);
        f0 = __uint_as_float(hp << 16); f1 = __uint_as_float(hp & 0xffff0000u);
        PACK_BF16X2(lp, v0 - f0, v1 - f1);
        *(uint32_t*)((__nv_bfloat16*)g_xh + base0 + 8 * DM + d) = hp;
        *(uint32_t*)((__nv_bfloat16*)g_xl + base0 + 8 * DM + d) = lp;
    }
}

// ============================================================
extern "C" void kernel_launch(void* const* d_in, const int* in_sizes, int n_in,
                              void* d_out, int out_size) {
    const float* Q  = (const float*)d_in[0];
    const float* K  = (const float*)d_in[1];
    const float* V  = (const float*)d_in[2];
    const int* mask = (const int*)d_in[3];
    const float* Wq = (const float*)d_in[4];
    const float* Wk = (const float*)d_in[5];
    const float* Wv = (const float*)d_in[6];
    const float* Wo = (const float*)d_in[7];
    float* out = (float*)d_out;

    static int attr_done = 0;
    if (!attr_done) {
        cudaFuncSetAttribute(proj_mma_kernel, cudaFuncAttributeMaxDynamicSharedMemorySize, SMEM_MMA);
        cudaFuncSetAttribute(out_mma_kernel, cudaFuncAttributeMaxDynamicSharedMemorySize, SMEM_MMA);
        cudaFuncSetAttribute(flash_mma_kernel, cudaFuncAttributeMaxDynamicSharedMemorySize, SMEM_FLASH);
        attr_done = 1;
    }

    prep_kernel<<<PREP_BLKS, 256>>>(mask, Q, K, V, Wq, Wk, Wv, Wo);
    proj_mma_kernel<<<dim3(DM / 128, MT / 128, 3), 256, SMEM_MMA>>>();
    flash_mma_kernel<<<dim3(NW / 128, NH, NB), 256, SMEM_FLASH>>>();
    out_mma_kernel<<<dim3(DM / 128, MT / 128), 256, SMEM_MMA>>>(out);
}

// round 14
// speedup vs baseline: 2.2897x; 1.4444x over previous
#include <cuda_runtime.h>
#include <cuda_fp16.h>
#include <cstdint>
#include <math.h>

#define NB 4
#define NW 2048
#define DM 1024
#define NH 16
#define DK 64
#define MT (NB*NW)
#define MWPR (NW/32)

// ---------------- device scratch ----------------
__device__ unsigned g_mb[NB*NW*MWPR];
__device__ __half g_x16[(size_t)3*MT*DM];   // Q,K,V inputs, single fp16
__device__ __half g_ao[(size_t)MT*DM];      // attention output, single fp16
__device__ __half g_wh16[(size_t)4*DM*DM];  // Wq,Wk,Wv,Wo hi
__device__ __half g_wl16[(size_t)4*DM*DM];  // lo
__device__ __half g_q16[NB*NH*NW*DK];       // q single fp16 (scale folded)
__device__ __half g_kh16[NB*NH*NW*DK];
__device__ __half g_kl16[NB*NH*NW*DK];
__device__ __half g_vh16[NB*NH*NW*DK];
__device__ __half g_vl16[NB*NH*NW*DK];

// ---------------- PTX helpers ----------------
__device__ __forceinline__ uint32_t smem_u32(const void* p) {
    uint32_t a;
    asm("{ .reg .u64 t; cvta.to.shared.u64 t, %1; cvt.u32.u64 %0, t; }" : "=r"(a) : "l"(p));
    return a;
}
#define CP_ASYNC16(sa, g) \
    asm volatile("cp.async.cg.shared.global [%0], [%1], 16;" :: "r"(sa), "l"(g))
#define CP_COMMIT() asm volatile("cp.async.commit_group;" ::: "memory")
#define CP_WAIT1()  asm volatile("cp.async.wait_group 1;" ::: "memory")
#define CP_WAIT0()  asm volatile("cp.async.wait_group 0;" ::: "memory")

#define LDSM4(r, addr) \
    asm volatile("ldmatrix.sync.aligned.m8n8.x4.shared.b16 {%0,%1,%2,%3}, [%4];" \
        : "=r"((r)[0]), "=r"((r)[1]), "=r"((r)[2]), "=r"((r)[3]) : "r"(addr))
#define LDSM4T(r, addr) \
    asm volatile("ldmatrix.sync.aligned.m8n8.x4.trans.shared.b16 {%0,%1,%2,%3}, [%4];" \
        : "=r"((r)[0]), "=r"((r)[1]), "=r"((r)[2]), "=r"((r)[3]) : "r"(addr))

#define MMAF16(d, a, b0, b1) \
    asm volatile("mma.sync.aligned.m16n8k16.row.col.f32.f16.f16.f32 " \
        "{%0,%1,%2,%3}, {%4,%5,%6,%7}, {%8,%9}, {%0,%1,%2,%3};" \
        : "+f"((d)[0]), "+f"((d)[1]), "+f"((d)[2]), "+f"((d)[3]) \
        : "r"((a)[0]), "r"((a)[1]), "r"((a)[2]), "r"((a)[3]), "r"(b0), "r"(b1))

// pack {low16=f16(lo), high16=f16(hi)}
#define PACK_F16X2(r, lo, hi) \
    asm("cvt.rn.f16x2.f32 %0, %1, %2;" : "=r"(r) : "f"(hi), "f"(lo))

// ---- GEMM smem geometry: CTA 128x128, 8 warps (4x2), warp 32x64, 2 stages ----
// tiles: X (single), Wh, Wl — each 128 rows x 32 halves, row stride 40
#define BKC    32
#define RS     40
#define X_OFF  0
#define WH_OFF 5120
#define WL_OFF 10240
#define STAGE_EL 15360
#define SMEM_MMA (2*STAGE_EL*2)         // 61440 B -> 2 CTAs/SM

// ---- flash smem geometry (Kh,Kl,Vh,Vl) ----
#define FRS    72
#define FTS    (64*FRS)
#define FSTAGE (4*FTS)
#define SMEM_FLASH (2*FSTAGE*2)          // 73728 B

#define NX_ELEMS  ((size_t)MT*DM)
#define NWT_ELEMS ((size_t)DM*DM)
#define PACK_BLKS  ((NB*NW*NW)/1024)     // 16384
#define CONVX_BLKS ((3*MT*DM)/1024)      // 24576
#define CONVW_BLKS ((4*DM*DM)/1024)      // 4096
#define PREP_BLKS  (PACK_BLKS + CONVX_BLKS + CONVW_BLKS)

// ============================================================
// prep: mask pack (int4 vectorized) + conversions
// ============================================================
__global__ void __launch_bounds__(256) prep_kernel(
    const int* __restrict__ mask,
    const float* __restrict__ Q, const float* __restrict__ K, const float* __restrict__ V,
    const float* __restrict__ Wq, const float* __restrict__ Wk,
    const float* __restrict__ Wv, const float* __restrict__ Wo)
{
    __shared__ uint8_t nib[256];
    int bid = blockIdx.x, tid = threadIdx.x;
    if (bid < PACK_BLKS) {
        const int4* mp = (const int4*)mask;
        int4 v = mp[(size_t)bid * 256 + tid];
        unsigned n = (unsigned)(v.x != 0) | ((unsigned)(v.y != 0) << 1)
                   | ((unsigned)(v.z != 0) << 2) | ((unsigned)(v.w != 0) << 3);
        nib[tid] = (uint8_t)n;
        __syncthreads();
        if (tid < 32) {
            const uint8_t* p = nib + tid * 8;
            unsigned w = 0;
            #pragma unroll
            for (int i = 0; i < 8; i++) w |= ((unsigned)p[i]) << (4 * i);
            g_mb[bid * 32 + tid] = w;
        }
        return;
    }
    bid -= PACK_BLKS;
    if (bid < CONVX_BLKS) {
        size_t i = ((size_t)bid * 256 + tid) * 4;
        const float* src; size_t off;
        if (i < NX_ELEMS)            { src = Q; off = i; }
        else if (i < 2 * NX_ELEMS)   { src = K; off = i - NX_ELEMS; }
        else                         { src = V; off = i - 2 * NX_ELEMS; }
        float4 v = *(const float4*)(src + off);
        ((__half2*)(g_x16 + i))[0] = __floats2half2_rn(v.x, v.y);
        ((__half2*)(g_x16 + i))[1] = __floats2half2_rn(v.z, v.w);
        return;
    }
    bid -= CONVX_BLKS;
    {
        size_t i = ((size_t)bid * 256 + tid) * 4;
        const float* src; size_t off;
        if (i < NWT_ELEMS)            { src = Wq; off = i; }
        else if (i < 2 * NWT_ELEMS)   { src = Wk; off = i - NWT_ELEMS; }
        else if (i < 3 * NWT_ELEMS)   { src = Wv; off = i - 2 * NWT_ELEMS; }
        else                          { src = Wo; off = i - 3 * NWT_ELEMS; }
        float4 v = *(const float4*)(src + off);
        __half h0 = __float2half_rn(v.x), h1 = __float2half_rn(v.y);
        __half h2 = __float2half_rn(v.z), h3 = __float2half_rn(v.w);
        __half l0 = __float2half_rn(v.x - __half2float(h0));
        __half l1 = __float2half_rn(v.y - __half2float(h1));
        __half l2 = __float2half_rn(v.z - __half2float(h2));
        __half l3 = __float2half_rn(v.w - __half2float(h3));
        ((__half2*)(g_wh16 + i))[0] = __halves2half2(h0, h1);
        ((__half2*)(g_wh16 + i))[1] = __halves2half2(h2, h3);
        ((__half2*)(g_wl16 + i))[0] = __halves2half2(l0, l1);
        ((__half2*)(g_wl16 + i))[1] = __halves2half2(l2, l3);
    }
}

// ============================================================
// GEMM: C[128x128] = X[m0:+128,:] * W[n0:+128,:]^T, 2-term fp16
// 256 threads, 8 warps (4x2), warp tile 32x64
// ============================================================
__device__ __forceinline__ void issue_stage(
    const __half* __restrict__ x,
    const __half* __restrict__ wh, const __half* __restrict__ wl,
    int m0, int n0, int kt, uint32_t stage_sb, int tid)
{
    #pragma unroll
    for (int t = 0; t < 6; t++) {
        int tile = t >> 1;                   // 0=X 1=Wh 2=Wl
        int rem = tid + (t & 1) * 256;       // 0..511
        int row = rem >> 2, cq = rem & 3;
        const __half* base = (tile == 0) ? x : (tile == 1) ? wh : wl;
        int rb = (tile == 0) ? m0 : n0;
        size_t g = (size_t)(rb + row) * DM + kt * BKC + cq * 8;
        uint32_t sa = stage_sb + (uint32_t)(tile * 5120 + row * RS + cq * 8) * 2;
        CP_ASYNC16(sa, base + g);
    }
}

__device__ __forceinline__ void mma_mainloop(
    const __half* __restrict__ x,
    const __half* __restrict__ wh, const __half* __restrict__ wl,
    int m0, int n0, __half* sbuf, float acc[2][8][4])
{
    int tid = threadIdx.x;
    int wid = tid >> 5, lane = tid & 31;
    int wm = wid >> 1, wn = wid & 1;
    int lr = lane & 15, lc = lane >> 4;

    uint32_t sb = smem_u32(sbuf);
    uint32_t stage_sb[2] = { sb, sb + (uint32_t)STAGE_EL * 2 };

    issue_stage(x, wh, wl, m0, n0, 0, stage_sb[0], tid);
    CP_COMMIT();

    for (int kt = 0; kt < DM / BKC; kt++) {
        int s = kt & 1;
        if (kt < DM / BKC - 1) {
            issue_stage(x, wh, wl, m0, n0, kt + 1, stage_sb[s ^ 1], tid);
            CP_COMMIT();
            CP_WAIT1();
        } else {
            CP_WAIT0();
        }
        __syncthreads();

        uint32_t ab = stage_sb[s];
        #pragma unroll
        for (int kk = 0; kk < BKC; kk += 16) {
            uint32_t af[2][4];
            #pragma unroll
            for (int mi = 0; mi < 2; mi++) {
                uint32_t off = (uint32_t)((wm * 32 + mi * 16 + lr) * RS + kk + lc * 8) * 2;
                LDSM4(af[mi], ab + X_OFF * 2 + off);
            }
            #pragma unroll
            for (int ni = 0; ni < 4; ni++) {
                uint32_t bh[4], bl[4];
                uint32_t off = (uint32_t)((wn * 64 + ni * 16 + lr) * RS + kk + lc * 8) * 2;
                LDSM4(bh, ab + WH_OFF * 2 + off);
                LDSM4(bl, ab + WL_OFF * 2 + off);
                #pragma unroll
                for (int mi = 0; mi < 2; mi++)
                    #pragma unroll
                    for (int hf = 0; hf < 2; hf++)
                        MMAF16(acc[mi][ni * 2 + hf], af[mi], bh[hf], bh[hf + 2]);
                #pragma unroll
                for (int mi = 0; mi < 2; mi++)
                    #pragma unroll
                    for (int hf = 0; hf < 2; hf++)
                        MMAF16(acc[mi][ni * 2 + hf], af[mi], bl[hf], bl[hf + 2]);
            }
        }
        __syncthreads();
    }
}

// ============================================================
// Projection GEMM: z=0 -> q single fp16 (scale folded); z=1/2 -> k/v hi+lo
// ============================================================
__global__ void __launch_bounds__(256, 2) proj_mma_kernel() {
    extern __shared__ __half sbuf[];
    int z = blockIdx.z;
    int m0 = blockIdx.y * 128, n0 = blockIdx.x * 128;
    const __half* x = g_x16 + (size_t)z * MT * DM;
    const __half* wh = g_wh16 + (size_t)z * DM * DM;
    const __half* wl = g_wl16 + (size_t)z * DM * DM;

    float acc[2][8][4];
    #pragma unroll
    for (int i = 0; i < 2; i++)
        #pragma unroll
        for (int j = 0; j < 8; j++)
            acc[i][j][0] = acc[i][j][1] = acc[i][j][2] = acc[i][j][3] = 0.f;

    mma_mainloop(x, wh, wl, m0, n0, sbuf, acc);

    int tid = threadIdx.x, wid = tid >> 5, lane = tid & 31;
    int wm = wid >> 1, wn = wid & 1;
    int h = (n0 + wn * 64) >> 6;
    float scale = (z == 0) ? 0.125f : 1.0f;
    __half* dh = (z == 1) ? g_kh16 : g_vh16;
    __half* dl = (z == 1) ? g_kl16 : g_vl16;

    #pragma unroll
    for (int mi = 0; mi < 2; mi++)
        #pragma unroll
        for (int nj = 0; nj < 8; nj++) {
            int d = nj * 8 + (lane & 3) * 2;
            int m = m0 + wm * 32 + mi * 16 + (lane >> 2);
            int bb = m >> 11, t = m & (NW - 1);
            size_t off0 = ((size_t)(bb * NH + h) * NW + t) * DK + d;
            size_t off1 = off0 + 8 * DK;
            float v00 = acc[mi][nj][0] * scale, v01 = acc[mi][nj][1] * scale;
            float v10 = acc[mi][nj][2] * scale, v11 = acc[mi][nj][3] * scale;
            if (z == 0) {
                *(__half2*)(g_q16 + off0) = __floats2half2_rn(v00, v01);
                *(__half2*)(g_q16 + off1) = __floats2half2_rn(v10, v11);
            } else {
                __half h0 = __float2half_rn(v00), h1 = __float2half_rn(v01);
                __half l0 = __float2half_rn(v00 - __half2float(h0));
                __half l1 = __float2half_rn(v01 - __half2float(h1));
                *(__half2*)(dh + off0) = __halves2half2(h0, h1);
                *(__half2*)(dl + off0) = __halves2half2(l0, l1);
                h0 = __float2half_rn(v10); h1 = __float2half_rn(v11);
                l0 = __float2half_rn(v10 - __half2float(h0));
                l1 = __float2half_rn(v11 - __half2float(h1));
                *(__half2*)(dh + off1) = __halves2half2(h0, h1);
                *(__half2*)(dl + off1) = __halves2half2(l0, l1);
            }
        }
}

// ============================================================
// Output GEMM: attn(single fp16) @ Wo^T (hi+lo) -> fp32
// ============================================================
__global__ void __launch_bounds__(256, 2) out_mma_kernel(float* __restrict__ out) {
    extern __shared__ __half sbuf[];
    int m0 = blockIdx.y * 128, n0 = blockIdx.x * 128;
    const __half* wh = g_wh16 + (size_t)3 * DM * DM;
    const __half* wl = g_wl16 + (size_t)3 * DM * DM;

    float acc[2][8][4];
    #pragma unroll
    for (int i = 0; i < 2; i++)
        #pragma unroll
        for (int j = 0; j < 8; j++)
            acc[i][j][0] = acc[i][j][1] = acc[i][j][2] = acc[i][j][3] = 0.f;

    mma_mainloop(g_ao, wh, wl, m0, n0, sbuf, acc);

    int tid = threadIdx.x, wid = tid >> 5, lane = tid & 31;
    int wm = wid >> 1, wn = wid & 1;
    #pragma unroll
    for (int mi = 0; mi < 2; mi++)
        #pragma unroll
        for (int nj = 0; nj < 8; nj++) {
            int n = n0 + wn * 64 + nj * 8 + (lane & 3) * 2;
            int m = m0 + wm * 32 + mi * 16 + (lane >> 2);
            *(float2*)(out + (size_t)m * DM + n) = make_float2(acc[mi][nj][0], acc[mi][nj][1]);
            *(float2*)(out + (size_t)(m + 8) * DM + n) = make_float2(acc[mi][nj][2], acc[mi][nj][3]);
        }
}

// ============================================================
// Flash attention: fp16 2-term; 256 threads, 8 warps, 16 q/warp, 2 CTAs/SM
// ============================================================
__device__ __forceinline__ void flash_issue(
    int kt, uint32_t stage_sb, int tid, size_t hb)
{
    const __half* gb[4] = { g_kh16 + hb, g_kl16 + hb, g_vh16 + hb, g_vl16 + hb };
    #pragma unroll
    for (int t = 0; t < 8; t++) {
        int tile = t >> 1;
        int rem = tid + (t & 1) * 256;
        int row = rem >> 3, cq = rem & 7;
        const __half* g = gb[tile] + (size_t)(kt * 64 + row) * DK + cq * 8;
        uint32_t sa = stage_sb + (uint32_t)(tile * FTS + row * FRS + cq * 8) * 2;
        CP_ASYNC16(sa, g);
    }
}

__global__ void __launch_bounds__(256, 2) flash_mma_kernel() {
    extern __shared__ __half fsm[];
    int b = blockIdx.z, h = blockIdx.y, q0 = blockIdx.x * 128;
    int tid = threadIdx.x, wid = tid >> 5, lane = tid & 31;
    int lr = lane & 15, lc = lane >> 4;
    int gr = lane >> 2, c = lane & 3;

    size_t hb = (size_t)(b * NH + h) * NW * DK;
    const __half* qp = g_q16 + hb + (size_t)q0 * DK;

    uint32_t qf[4][4];
    #pragma unroll
    for (int kc = 0; kc < 4; kc++) {
        int r0 = wid * 16 + gr, col = kc * 16 + 2 * c;
        qf[kc][0] = *(const uint32_t*)(qp + (size_t)r0 * DK + col);
        qf[kc][1] = *(const uint32_t*)(qp + (size_t)(r0 + 8) * DK + col);
        qf[kc][2] = *(const uint32_t*)(qp + (size_t)r0 * DK + col + 8);
        qf[kc][3] = *(const uint32_t*)(qp + (size_t)(r0 + 8) * DK + col + 8);
    }

    float oacc[8][4];
    #pragma unroll
    for (int j = 0; j < 8; j++)
        oacc[j][0] = oacc[j][1] = oacc[j][2] = oacc[j][3] = 0.f;
    float m0 = -INFINITY, m1 = -INFINITY, l0 = 0.f, l1 = 0.f;

    uint32_t sb = smem_u32(fsm);
    flash_issue(0, sb, tid, hb);
    CP_COMMIT();

    for (int kt = 0; kt < NW / 64; kt++) {
        int s = kt & 1;
        uint32_t ss = sb + (uint32_t)(s * FSTAGE) * 2;
        if (kt < NW / 64 - 1) {
            flash_issue(kt + 1, sb + (uint32_t)((s ^ 1) * FSTAGE) * 2, tid, hb);
            CP_COMMIT();
            CP_WAIT1();
        } else {
            CP_WAIT0();
        }
        __syncthreads();

        const unsigned* mb0 = g_mb + (size_t)(b * NW + q0 + wid * 16 + gr) * MWPR + kt * 2;
        unsigned mw00 = mb0[0], mw01 = mb0[1];
        unsigned mw10 = mb0[8 * MWPR], mw11 = mb0[8 * MWPR + 1];

        float sacc[8][4];
        #pragma unroll
        for (int j = 0; j < 8; j++)
            sacc[j][0] = sacc[j][1] = sacc[j][2] = sacc[j][3] = 0.f;

        #pragma unroll
        for (int kc = 0; kc < 4; kc++) {
            #pragma unroll
            for (int g = 0; g < 4; g++) {
                uint32_t khf[4], klf[4];
                uint32_t off = (uint32_t)((g * 16 + lr) * FRS + kc * 16 + lc * 8) * 2;
                LDSM4(khf, ss + off);
                LDSM4(klf, ss + (uint32_t)FTS * 2 + off);
                #pragma unroll
                for (int hf = 0; hf < 2; hf++)
                    MMAF16(sacc[2 * g + hf], qf[kc], khf[hf], khf[hf + 2]);
                #pragma unroll
                for (int hf = 0; hf < 2; hf++)
                    MMAF16(sacc[2 * g + hf], qf[kc], klf[hf], klf[hf + 2]);
            }
        }

        #pragma unroll
        for (int j = 0; j < 8; j++) {
            unsigned wr0 = (j < 4) ? mw00 : mw01;
            unsigned wr1 = (j < 4) ? mw10 : mw11;
            int bit = (8 * j + 2 * c) & 31;
            if (!((wr0 >> bit) & 1u))       sacc[j][0] = -1e9f;
            if (!((wr0 >> (bit + 1)) & 1u)) sacc[j][1] = -1e9f;
            if (!((wr1 >> bit) & 1u))       sacc[j][2] = -1e9f;
            if (!((wr1 >> (bit + 1)) & 1u)) sacc[j][3] = -1e9f;
        }

        float mx0 = -INFINITY, mx1 = -INFINITY;
        #pragma unroll
        for (int j = 0; j < 8; j++) {
            mx0 = fmaxf(mx0, fmaxf(sacc[j][0], sacc[j][1]));
            mx1 = fmaxf(mx1, fmaxf(sacc[j][2], sacc[j][3]));
        }
        mx0 = fmaxf(mx0, __shfl_xor_sync(0xffffffffu, mx0, 1));
        mx0 = fmaxf(mx0, __shfl_xor_sync(0xffffffffu, mx0, 2));
        mx1 = fmaxf(mx1, __shfl_xor_sync(0xffffffffu, mx1, 1));
        mx1 = fmaxf(mx1, __shfl_xor_sync(0xffffffffu, mx1, 2));

        float nm0 = fmaxf(m0, mx0), nm1 = fmaxf(m1, mx1);
        float sc0 = __expf(m0 - nm0), sc1 = __expf(m1 - nm1);
        float rs0 = 0.f, rs1 = 0.f;
        #pragma unroll
        for (int j = 0; j < 8; j++) {
            sacc[j][0] = __expf(sacc[j][0] - nm0);
            sacc[j][1] = __expf(sacc[j][1] - nm0);
            sacc[j][2] = __expf(sacc[j][2] - nm1);
            sacc[j][3] = __expf(sacc[j][3] - nm1);
            rs0 += sacc[j][0] + sacc[j][1];
            rs1 += sacc[j][2] + sacc[j][3];
        }
        rs0 += __shfl_xor_sync(0xffffffffu, rs0, 1);
        rs0 += __shfl_xor_sync(0xffffffffu, rs0, 2);
        rs1 += __shfl_xor_sync(0xffffffffu, rs1, 1);
        rs1 += __shfl_xor_sync(0xffffffffu, rs1, 2);
        m0 = nm0; m1 = nm1;
        l0 = l0 * sc0 + rs0;
        l1 = l1 * sc1 + rs1;
        #pragma unroll
        for (int j = 0; j < 8; j++) {
            oacc[j][0] *= sc0; oacc[j][1] *= sc0;
            oacc[j][2] *= sc1; oacc[j][3] *= sc1;
        }

        // P: single fp16 digit
        uint32_t pf[4][4];
        #pragma unroll
        for (int kc = 0; kc < 4; kc++) {
            #pragma unroll
            for (int q = 0; q < 4; q++) {
                int jt = 2 * kc + (q >> 1);
                float p0 = sacc[jt][(q & 1) ? 2 : 0];
                float p1 = sacc[jt][(q & 1) ? 3 : 1];
                uint32_t hp;
                PACK_F16X2(hp, p0, p1);
                pf[kc][q] = hp;
            }
        }

        #pragma unroll
        for (int kc = 0; kc < 4; kc++) {
            #pragma unroll
            for (int dg = 0; dg < 4; dg++) {
                uint32_t vhf[4], vlf[4];
                uint32_t off = (uint32_t)((kc * 16 + lr) * FRS + dg * 16 + lc * 8) * 2;
                LDSM4T(vhf, ss + (uint32_t)(2 * FTS) * 2 + off);
                LDSM4T(vlf, ss + (uint32_t)(3 * FTS) * 2 + off);
                MMAF16(oacc[2 * dg],     pf[kc], vhf[0], vhf[1]);
                MMAF16(oacc[2 * dg + 1], pf[kc], vhf[2], vhf[3]);
                MMAF16(oacc[2 * dg],     pf[kc], vlf[0], vlf[1]);
                MMAF16(oacc[2 * dg + 1], pf[kc], vlf[2], vlf[3]);
            }
        }
        __syncthreads();
    }

    float inv0 = 1.f / l0, inv1 = 1.f / l1;
    int row0 = q0 + wid * 16 + gr;
    size_t base0 = ((size_t)b * NW + row0) * DM + h * DK;
    #pragma unroll
    for (int j = 0; j < 8; j++) {
        int d = 8 * j + 2 * c;
        *(__half2*)(g_ao + base0 + d) =
            __floats2half2_rn(oacc[j][0] * inv0, oacc[j][1] * inv0);
        *(__half2*)(g_ao + base0 + 8 * DM + d) =
            __floats2half2_rn(oacc[j][2] * inv1, oacc[j][3] * inv1);
    }
}

// ============================================================
extern "C" void kernel_launch(void* const* d_in, const int* in_sizes, int n_in,
                              void* d_out, int out_size) {
    const float* Q  = (const float*)d_in[0];
    const float* K  = (const float*)d_in[1];
    const float* V  = (const float*)d_in[2];
    const int* mask = (const int*)d_in[3];
    const float* Wq = (const float*)d_in[4];
    const float* Wk = (const float*)d_in[5];
    const float* Wv = (const float*)d_in[6];
    const float* Wo = (const float*)d_in[7];
    float* out = (float*)d_out;

    static int attr_done = 0;
    if (!attr_done) {
        cudaFuncSetAttribute(proj_mma_kernel, cudaFuncAttributeMaxDynamicSharedMemorySize, SMEM_MMA);
        cudaFuncSetAttribute(out_mma_kernel, cudaFuncAttributeMaxDynamicSharedMemorySize, SMEM_MMA);
        cudaFuncSetAttribute(flash_mma_kernel, cudaFuncAttributeMaxDynamicSharedMemorySize, SMEM_FLASH);
        attr_done = 1;
    }

    prep_kernel<<<PREP_BLKS, 256>>>(mask, Q, K, V, Wq, Wk, Wv, Wo);
    proj_mma_kernel<<<dim3(DM / 128, MT / 128, 3), 256, SMEM_MMA>>>();
    flash_mma_kernel<<<dim3(NW / 128, NH, NB), 256, SMEM_FLASH>>>();
    out_mma_kernel<<<dim3(DM / 128, MT / 128), 256, SMEM_MMA>>>(out);
}

// round 15
// speedup vs baseline: 3.6146x; 1.5786x over previous
#include <cuda_runtime.h>
#include <cuda_fp16.h>
#include <cstdint>
#include <math.h>

#define NB 4
#define NW 2048
#define DM 1024
#define NH 16
#define DK 64
#define MT (NB*NW)
#define MWPR (NW/32)

// ---------------- device scratch ----------------
__device__ unsigned g_mb[NB*NW*MWPR];
__device__ __half g_x16[(size_t)3*MT*DM];   // Q,K,V inputs fp16
__device__ __half g_ao[(size_t)MT*DM];      // attention output fp16
__device__ __half g_w16[(size_t)4*DM*DM];   // Wq,Wk,Wv,Wo fp16
__device__ __half g_q16[NB*NH*NW*DK];       // q (scale folded)
__device__ __half g_k16[NB*NH*NW*DK];
__device__ __half g_v16[NB*NH*NW*DK];

// ---------------- PTX helpers ----------------
__device__ __forceinline__ uint32_t smem_u32(const void* p) {
    uint32_t a;
    asm("{ .reg .u64 t; cvta.to.shared.u64 t, %1; cvt.u32.u64 %0, t; }" : "=r"(a) : "l"(p));
    return a;
}
#define CP_ASYNC16(sa, g) \
    asm volatile("cp.async.cg.shared.global [%0], [%1], 16;" :: "r"(sa), "l"(g))
#define CP_COMMIT() asm volatile("cp.async.commit_group;" ::: "memory")
#define CP_WAIT1()  asm volatile("cp.async.wait_group 1;" ::: "memory")
#define CP_WAIT0()  asm volatile("cp.async.wait_group 0;" ::: "memory")

#define LDSM4(r, addr) \
    asm volatile("ldmatrix.sync.aligned.m8n8.x4.shared.b16 {%0,%1,%2,%3}, [%4];" \
        : "=r"((r)[0]), "=r"((r)[1]), "=r"((r)[2]), "=r"((r)[3]) : "r"(addr))
#define LDSM4T(r, addr) \
    asm volatile("ldmatrix.sync.aligned.m8n8.x4.trans.shared.b16 {%0,%1,%2,%3}, [%4];" \
        : "=r"((r)[0]), "=r"((r)[1]), "=r"((r)[2]), "=r"((r)[3]) : "r"(addr))

#define MMAF16(d, a, b0, b1) \
    asm volatile("mma.sync.aligned.m16n8k16.row.col.f32.f16.f16.f32 " \
        "{%0,%1,%2,%3}, {%4,%5,%6,%7}, {%8,%9}, {%0,%1,%2,%3};" \
        : "+f"((d)[0]), "+f"((d)[1]), "+f"((d)[2]), "+f"((d)[3]) \
        : "r"((a)[0]), "r"((a)[1]), "r"((a)[2]), "r"((a)[3]), "r"(b0), "r"(b1))

#define PACK_F16X2(r, lo, hi) \
    asm("cvt.rn.f16x2.f32 %0, %1, %2;" : "=r"(r) : "f"(hi), "f"(lo))

// ---- GEMM smem geometry: CTA 128x128, 8 warps (4x2), warp 32x64, 2 stages ----
// tiles: X, W — each 128 rows x 32 halves, row stride 40
#define BKC    32
#define RS     40
#define X_OFF  0
#define W_OFF  5120
#define STAGE_EL 10240
#define SMEM_MMA (2*STAGE_EL*2)         // 40960 B -> 2 CTAs/SM

// ---- flash smem geometry (K, V single) ----
#define FRS    72
#define FTS    (64*FRS)
#define FSTAGE (2*FTS)
#define SMEM_FLASH (2*FSTAGE*2)          // 36864 B

#define NX_ELEMS  ((size_t)MT*DM)
#define NWT_ELEMS ((size_t)DM*DM)
#define PACK_BLKS  ((NB*NW*NW)/1024)     // 16384
#define CONVX_BLKS ((3*MT*DM)/1024)      // 24576
#define CONVW_BLKS ((4*DM*DM)/1024)      // 4096
#define PREP_BLKS  (PACK_BLKS + CONVX_BLKS + CONVW_BLKS)

// ============================================================
// prep: mask pack (int4 vectorized) + fp32->fp16 conversions
// ============================================================
__global__ void __launch_bounds__(256) prep_kernel(
    const int* __restrict__ mask,
    const float* __restrict__ Q, const float* __restrict__ K, const float* __restrict__ V,
    const float* __restrict__ Wq, const float* __restrict__ Wk,
    const float* __restrict__ Wv, const float* __restrict__ Wo)
{
    __shared__ uint8_t nib[256];
    int bid = blockIdx.x, tid = threadIdx.x;
    if (bid < PACK_BLKS) {
        const int4* mp = (const int4*)mask;
        int4 v = mp[(size_t)bid * 256 + tid];
        unsigned n = (unsigned)(v.x != 0) | ((unsigned)(v.y != 0) << 1)
                   | ((unsigned)(v.z != 0) << 2) | ((unsigned)(v.w != 0) << 3);
        nib[tid] = (uint8_t)n;
        __syncthreads();
        if (tid < 32) {
            const uint8_t* p = nib + tid * 8;
            unsigned w = 0;
            #pragma unroll
            for (int i = 0; i < 8; i++) w |= ((unsigned)p[i]) << (4 * i);
            g_mb[bid * 32 + tid] = w;
        }
        return;
    }
    bid -= PACK_BLKS;
    if (bid < CONVX_BLKS) {
        size_t i = ((size_t)bid * 256 + tid) * 4;
        const float* src; size_t off;
        if (i < NX_ELEMS)            { src = Q; off = i; }
        else if (i < 2 * NX_ELEMS)   { src = K; off = i - NX_ELEMS; }
        else                         { src = V; off = i - 2 * NX_ELEMS; }
        float4 v = *(const float4*)(src + off);
        ((__half2*)(g_x16 + i))[0] = __floats2half2_rn(v.x, v.y);
        ((__half2*)(g_x16 + i))[1] = __floats2half2_rn(v.z, v.w);
        return;
    }
    bid -= CONVX_BLKS;
    {
        size_t i = ((size_t)bid * 256 + tid) * 4;
        const float* src; size_t off;
        if (i < NWT_ELEMS)            { src = Wq; off = i; }
        else if (i < 2 * NWT_ELEMS)   { src = Wk; off = i - NWT_ELEMS; }
        else if (i < 3 * NWT_ELEMS)   { src = Wv; off = i - 2 * NWT_ELEMS; }
        else                          { src = Wo; off = i - 3 * NWT_ELEMS; }
        float4 v = *(const float4*)(src + off);
        ((__half2*)(g_w16 + i))[0] = __floats2half2_rn(v.x, v.y);
        ((__half2*)(g_w16 + i))[1] = __floats2half2_rn(v.z, v.w);
    }
}

// ============================================================
// GEMM: C[128x128] = X[m0:+128,:] * W[n0:+128,:]^T, pure fp16 1-term
// 256 threads, 8 warps (4x2), warp tile 32x64
// ============================================================
__device__ __forceinline__ void issue_stage(
    const __half* __restrict__ x, const __half* __restrict__ w,
    int m0, int n0, int kt, uint32_t stage_sb, int tid)
{
    #pragma unroll
    for (int t = 0; t < 4; t++) {
        int tile = t >> 1;                   // 0=X 1=W
        int rem = tid + (t & 1) * 256;       // 0..511
        int row = rem >> 2, cq = rem & 3;
        const __half* base = (tile == 0) ? x : w;
        int rb = (tile == 0) ? m0 : n0;
        size_t g = (size_t)(rb + row) * DM + kt * BKC + cq * 8;
        uint32_t sa = stage_sb + (uint32_t)(tile * 5120 + row * RS + cq * 8) * 2;
        CP_ASYNC16(sa, base + g);
    }
}

__device__ __forceinline__ void mma_mainloop(
    const __half* __restrict__ x, const __half* __restrict__ w,
    int m0, int n0, __half* sbuf, float acc[2][8][4])
{
    int tid = threadIdx.x;
    int wid = tid >> 5, lane = tid & 31;
    int wm = wid >> 1, wn = wid & 1;
    int lr = lane & 15, lc = lane >> 4;

    uint32_t sb = smem_u32(sbuf);
    uint32_t stage_sb[2] = { sb, sb + (uint32_t)STAGE_EL * 2 };

    issue_stage(x, w, m0, n0, 0, stage_sb[0], tid);
    CP_COMMIT();

    for (int kt = 0; kt < DM / BKC; kt++) {
        int s = kt & 1;
        if (kt < DM / BKC - 1) {
            issue_stage(x, w, m0, n0, kt + 1, stage_sb[s ^ 1], tid);
            CP_COMMIT();
            CP_WAIT1();
        } else {
            CP_WAIT0();
        }
        __syncthreads();

        uint32_t ab = stage_sb[s];
        #pragma unroll
        for (int kk = 0; kk < BKC; kk += 16) {
            uint32_t af[2][4];
            #pragma unroll
            for (int mi = 0; mi < 2; mi++) {
                uint32_t off = (uint32_t)((wm * 32 + mi * 16 + lr) * RS + kk + lc * 8) * 2;
                LDSM4(af[mi], ab + X_OFF * 2 + off);
            }
            #pragma unroll
            for (int ni = 0; ni < 4; ni++) {
                uint32_t bf[4];
                uint32_t off = (uint32_t)((wn * 64 + ni * 16 + lr) * RS + kk + lc * 8) * 2;
                LDSM4(bf, ab + W_OFF * 2 + off);
                #pragma unroll
                for (int mi = 0; mi < 2; mi++)
                    #pragma unroll
                    for (int hf = 0; hf < 2; hf++)
                        MMAF16(acc[mi][ni * 2 + hf], af[mi], bf[hf], bf[hf + 2]);
            }
        }
        __syncthreads();
    }
}

// ============================================================
// Projection GEMM: writes fp16 head-major q/k/v
// ============================================================
__global__ void __launch_bounds__(256, 2) proj_mma_kernel() {
    extern __shared__ __half sbuf[];
    int z = blockIdx.z;
    int m0 = blockIdx.y * 128, n0 = blockIdx.x * 128;
    const __half* x = g_x16 + (size_t)z * MT * DM;
    const __half* w = g_w16 + (size_t)z * DM * DM;
    __half* dst = (z == 0) ? g_q16 : (z == 1) ? g_k16 : g_v16;
    float scale = (z == 0) ? 0.125f : 1.0f;

    float acc[2][8][4];
    #pragma unroll
    for (int i = 0; i < 2; i++)
        #pragma unroll
        for (int j = 0; j < 8; j++)
            acc[i][j][0] = acc[i][j][1] = acc[i][j][2] = acc[i][j][3] = 0.f;

    mma_mainloop(x, w, m0, n0, sbuf, acc);

    int tid = threadIdx.x, wid = tid >> 5, lane = tid & 31;
    int wm = wid >> 1, wn = wid & 1;
    int h = (n0 + wn * 64) >> 6;
    #pragma unroll
    for (int mi = 0; mi < 2; mi++)
        #pragma unroll
        for (int nj = 0; nj < 8; nj++) {
            int d = nj * 8 + (lane & 3) * 2;
            int m = m0 + wm * 32 + mi * 16 + (lane >> 2);
            int bb = m >> 11, t = m & (NW - 1);
            size_t off0 = ((size_t)(bb * NH + h) * NW + t) * DK + d;
            *(__half2*)(dst + off0) =
                __floats2half2_rn(acc[mi][nj][0] * scale, acc[mi][nj][1] * scale);
            *(__half2*)(dst + off0 + 8 * DK) =
                __floats2half2_rn(acc[mi][nj][2] * scale, acc[mi][nj][3] * scale);
        }
}

// ============================================================
// Output GEMM: attn(fp16) @ Wo^T(fp16) -> fp32
// ============================================================
__global__ void __launch_bounds__(256, 2) out_mma_kernel(float* __restrict__ out) {
    extern __shared__ __half sbuf[];
    int m0 = blockIdx.y * 128, n0 = blockIdx.x * 128;
    const __half* w = g_w16 + (size_t)3 * DM * DM;

    float acc[2][8][4];
    #pragma unroll
    for (int i = 0; i < 2; i++)
        #pragma unroll
        for (int j = 0; j < 8; j++)
            acc[i][j][0] = acc[i][j][1] = acc[i][j][2] = acc[i][j][3] = 0.f;

    mma_mainloop(g_ao, w, m0, n0, sbuf, acc);

    int tid = threadIdx.x, wid = tid >> 5, lane = tid & 31;
    int wm = wid >> 1, wn = wid & 1;
    #pragma unroll
    for (int mi = 0; mi < 2; mi++)
        #pragma unroll
        for (int nj = 0; nj < 8; nj++) {
            int n = n0 + wn * 64 + nj * 8 + (lane & 3) * 2;
            int m = m0 + wm * 32 + mi * 16 + (lane >> 2);
            *(float2*)(out + (size_t)m * DM + n) = make_float2(acc[mi][nj][0], acc[mi][nj][1]);
            *(float2*)(out + (size_t)(m + 8) * DM + n) = make_float2(acc[mi][nj][2], acc[mi][nj][3]);
        }
}

// ============================================================
// Flash attention: pure fp16; 256 threads, 8 warps, 16 q/warp, 2 CTAs/SM
// ============================================================
__device__ __forceinline__ void flash_issue(
    int kt, uint32_t stage_sb, int tid, size_t hb)
{
    const __half* gb[2] = { g_k16 + hb, g_v16 + hb };
    #pragma unroll
    for (int t = 0; t < 4; t++) {
        int tile = t >> 1;
        int rem = tid + (t & 1) * 256;
        int row = rem >> 3, cq = rem & 7;
        const __half* g = gb[tile] + (size_t)(kt * 64 + row) * DK + cq * 8;
        uint32_t sa = stage_sb + (uint32_t)(tile * FTS + row * FRS + cq * 8) * 2;
        CP_ASYNC16(sa, g);
    }
}

__global__ void __launch_bounds__(256, 2) flash_mma_kernel() {
    extern __shared__ __half fsm[];
    int b = blockIdx.z, h = blockIdx.y, q0 = blockIdx.x * 128;
    int tid = threadIdx.x, wid = tid >> 5, lane = tid & 31;
    int lr = lane & 15, lc = lane >> 4;
    int gr = lane >> 2, c = lane & 3;

    size_t hb = (size_t)(b * NH + h) * NW * DK;
    const __half* qp = g_q16 + hb + (size_t)q0 * DK;

    uint32_t qf[4][4];
    #pragma unroll
    for (int kc = 0; kc < 4; kc++) {
        int r0 = wid * 16 + gr, col = kc * 16 + 2 * c;
        qf[kc][0] = *(const uint32_t*)(qp + (size_t)r0 * DK + col);
        qf[kc][1] = *(const uint32_t*)(qp + (size_t)(r0 + 8) * DK + col);
        qf[kc][2] = *(const uint32_t*)(qp + (size_t)r0 * DK + col + 8);
        qf[kc][3] = *(const uint32_t*)(qp + (size_t)(r0 + 8) * DK + col + 8);
    }

    float oacc[8][4];
    #pragma unroll
    for (int j = 0; j < 8; j++)
        oacc[j][0] = oacc[j][1] = oacc[j][2] = oacc[j][3] = 0.f;
    float m0 = -INFINITY, m1 = -INFINITY, l0 = 0.f, l1 = 0.f;

    uint32_t sb = smem_u32(fsm);
    flash_issue(0, sb, tid, hb);
    CP_COMMIT();

    for (int kt = 0; kt < NW / 64; kt++) {
        int s = kt & 1;
        uint32_t ss = sb + (uint32_t)(s * FSTAGE) * 2;
        if (kt < NW / 64 - 1) {
            flash_issue(kt + 1, sb + (uint32_t)((s ^ 1) * FSTAGE) * 2, tid, hb);
            CP_COMMIT();
            CP_WAIT1();
        } else {
            CP_WAIT0();
        }
        __syncthreads();

        const unsigned* mb0 = g_mb + (size_t)(b * NW + q0 + wid * 16 + gr) * MWPR + kt * 2;
        unsigned mw00 = mb0[0], mw01 = mb0[1];
        unsigned mw10 = mb0[8 * MWPR], mw11 = mb0[8 * MWPR + 1];

        float sacc[8][4];
        #pragma unroll
        for (int j = 0; j < 8; j++)
            sacc[j][0] = sacc[j][1] = sacc[j][2] = sacc[j][3] = 0.f;

        #pragma unroll
        for (int kc = 0; kc < 4; kc++) {
            #pragma unroll
            for (int g = 0; g < 4; g++) {
                uint32_t kf[4];
                uint32_t off = (uint32_t)((g * 16 + lr) * FRS + kc * 16 + lc * 8) * 2;
                LDSM4(kf, ss + off);
                #pragma unroll
                for (int hf = 0; hf < 2; hf++)
                    MMAF16(sacc[2 * g + hf], qf[kc], kf[hf], kf[hf + 2]);
            }
        }

        #pragma unroll
        for (int j = 0; j < 8; j++) {
            unsigned wr0 = (j < 4) ? mw00 : mw01;
            unsigned wr1 = (j < 4) ? mw10 : mw11;
            int bit = (8 * j + 2 * c) & 31;
            if (!((wr0 >> bit) & 1u))       sacc[j][0] = -1e9f;
            if (!((wr0 >> (bit + 1)) & 1u)) sacc[j][1] = -1e9f;
            if (!((wr1 >> bit) & 1u))       sacc[j][2] = -1e9f;
            if (!((wr1 >> (bit + 1)) & 1u)) sacc[j][3] = -1e9f;
        }

        float mx0 = -INFINITY, mx1 = -INFINITY;
        #pragma unroll
        for (int j = 0; j < 8; j++) {
            mx0 = fmaxf(mx0, fmaxf(sacc[j][0], sacc[j][1]));
            mx1 = fmaxf(mx1, fmaxf(sacc[j][2], sacc[j][3]));
        }
        mx0 = fmaxf(mx0, __shfl_xor_sync(0xffffffffu, mx0, 1));
        mx0 = fmaxf(mx0, __shfl_xor_sync(0xffffffffu, mx0, 2));
        mx1 = fmaxf(mx1, __shfl_xor_sync(0xffffffffu, mx1, 1));
        mx1 = fmaxf(mx1, __shfl_xor_sync(0xffffffffu, mx1, 2));

        float nm0 = fmaxf(m0, mx0), nm1 = fmaxf(m1, mx1);
        float sc0 = __expf(m0 - nm0), sc1 = __expf(m1 - nm1);
        float rs0 = 0.f, rs1 = 0.f;
        #pragma unroll
        for (int j = 0; j < 8; j++) {
            sacc[j][0] = __expf(sacc[j][0] - nm0);
            sacc[j][1] = __expf(sacc[j][1] - nm0);
            sacc[j][2] = __expf(sacc[j][2] - nm1);
            sacc[j][3] = __expf(sacc[j][3] - nm1);
            rs0 += sacc[j][0] + sacc[j][1];
            rs1 += sacc[j][2] + sacc[j][3];
        }
        rs0 += __shfl_xor_sync(0xffffffffu, rs0, 1);
        rs0 += __shfl_xor_sync(0xffffffffu, rs0, 2);
        rs1 += __shfl_xor_sync(0xffffffffu, rs1, 1);
        rs1 += __shfl_xor_sync(0xffffffffu, rs1, 2);
        m0 = nm0; m1 = nm1;
        l0 = l0 * sc0 + rs0;
        l1 = l1 * sc1 + rs1;
        #pragma unroll
        for (int j = 0; j < 8; j++) {
            oacc[j][0] *= sc0; oacc[j][1] *= sc0;
            oacc[j][2] *= sc1; oacc[j][3] *= sc1;
        }

        uint32_t pf[4][4];
        #pragma unroll
        for (int kc = 0; kc < 4; kc++) {
            #pragma unroll
            for (int q = 0; q < 4; q++) {
                int jt = 2 * kc + (q >> 1);
                float p0 = sacc[jt][(q & 1) ? 2 : 0];
                float p1 = sacc[jt][(q & 1) ? 3 : 1];
                uint32_t hp;
                PACK_F16X2(hp, p0, p1);
                pf[kc][q] = hp;
            }
        }

        #pragma unroll
        for (int kc = 0; kc < 4; kc++) {
            #pragma unroll
            for (int dg = 0; dg < 4; dg++) {
                uint32_t vf[4];
                uint32_t off = (uint32_t)((kc * 16 + lr) * FRS + dg * 16 + lc * 8) * 2;
                LDSM4T(vf, ss + (uint32_t)FTS * 2 + off);
                MMAF16(oacc[2 * dg],     pf[kc], vf[0], vf[1]);
                MMAF16(oacc[2 * dg + 1], pf[kc], vf[2], vf[3]);
            }
        }
        __syncthreads();
    }

    float inv0 = 1.f / l0, inv1 = 1.f / l1;
    int row0 = q0 + wid * 16 + gr;
    size_t base0 = ((size_t)b * NW + row0) * DM + h * DK;
    #pragma unroll
    for (int j = 0; j < 8; j++) {
        int d = 8 * j + 2 * c;
        *(__half2*)(g_ao + base0 + d) =
            __floats2half2_rn(oacc[j][0] * inv0, oacc[j][1] * inv0);
        *(__half2*)(g_ao + base0 + 8 * DM + d) =
            __floats2half2_rn(oacc[j][2] * inv1, oacc[j][3] * inv1);
    }
}

// ============================================================
extern "C" void kernel_launch(void* const* d_in, const int* in_sizes, int n_in,
                              void* d_out, int out_size) {
    const float* Q  = (const float*)d_in[0];
    const float* K  = (const float*)d_in[1];
    const float* V  = (const float*)d_in[2];
    const int* mask = (const int*)d_in[3];
    const float* Wq = (const float*)d_in[4];
    const float* Wk = (const float*)d_in[5];
    const float* Wv = (const float*)d_in[6];
    const float* Wo = (const float*)d_in[7];
    float* out = (float*)d_out;

    static int attr_done = 0;
    if (!attr_done) {
        cudaFuncSetAttribute(proj_mma_kernel, cudaFuncAttributeMaxDynamicSharedMemorySize, SMEM_MMA);
        cudaFuncSetAttribute(out_mma_kernel, cudaFuncAttributeMaxDynamicSharedMemorySize, SMEM_MMA);
        cudaFuncSetAttribute(flash_mma_kernel, cudaFuncAttributeMaxDynamicSharedMemorySize, SMEM_FLASH);
        attr_done = 1;
    }

    prep_kernel<<<PREP_BLKS, 256>>>(mask, Q, K, V, Wq, Wk, Wv, Wo);
    proj_mma_kernel<<<dim3(DM / 128, MT / 128, 3), 256, SMEM_MMA>>>();
    flash_mma_kernel<<<dim3(NW / 128, NH, NB), 256, SMEM_FLASH>>>();
    out_mma_kernel<<<dim3(DM / 128, MT / 128), 256, SMEM_MMA>>>(out);
}